// round 12
// baseline (speedup 1.0000x reference)
#include <cuda_runtime.h>
#include <cuda_bf16.h>
#include <math.h>
#include <stdint.h>

// ---------------------------------------------------------------------------
// Problem constants (FixedSpectralBlock: B=4, T=4096, C=1024, K=1024)
// ---------------------------------------------------------------------------
#define Bb   4
#define Tt   4096
#define Cc   1024
#define Kk   1024
#define NFFT 8192
#define FB   4097          // NFFT/2 + 1
#define Hh   2048          // 2*C
#define EPSv 1e-5f
#define NROWS (Bb*Tt)
#define NSP  16            // pooled T-splits

// Scratch layout inside d_out rows 0..127 of batch 0 (conv pass-1 skips that
// tile; fixup reads scratch then overwrites it). Offsets in floats:
#define OFF_H    0        // hfilt          [8192]
#define OFF_WRE  8192     // W.re           [4160]
#define OFF_WIM  12352    // W.im           [4160]
#define OFF_MU   16512    // LN1 mean       [16384]
#define OFF_RS   32896    // LN1 rstd       [16384]
#define OFF_S    49280    // per-batch S    [8]
#define OFF_PL   49288    // pooled         [4096]
#define OFF_GC   53384    // gctx           [4096]
#define OFF_FLAG 58368    // fixup spin-barrier flag
#define OFF_PP   58376    // pooled partials [Bb*NSP*Cc = 65536] (end 123912)

// ---------------------------------------------------------------------------
// Helpers
// ---------------------------------------------------------------------------
__device__ __forceinline__ float2 block_reduce2(float a, float b) {
    __shared__ float sa[8], sb[8];
    for (int o = 16; o > 0; o >>= 1) {
        a += __shfl_xor_sync(0xFFFFFFFFu, a, o);
        b += __shfl_xor_sync(0xFFFFFFFFu, b, o);
    }
    int w = threadIdx.x >> 5, l = threadIdx.x & 31;
    if (l == 0) { sa[w] = a; sb[w] = b; }
    __syncthreads();
    if (w == 0) {
        a = (l < 8) ? sa[l] : 0.f;
        b = (l < 8) ? sb[l] : 0.f;
        for (int o = 4; o > 0; o >>= 1) {
            a += __shfl_xor_sync(0xFFFFFFFFu, a, o);
            b += __shfl_xor_sync(0xFFFFFFFFu, b, o);
        }
        if (l == 0) { sa[0] = a; sb[0] = b; }
    }
    __syncthreads();
    return make_float2(sa[0], sb[0]);
}

__device__ __forceinline__ uint32_t pack_bf2(float lo, float hi) {
    __nv_bfloat162 h = __floats2bfloat162_rn(lo, hi);
    return *reinterpret_cast<uint32_t*>(&h);
}

__device__ __forceinline__ uint32_t smem_cast(const void* p) {
    return (uint32_t)__cvta_generic_to_shared(p);
}

__device__ __forceinline__ void ldsm4(uint32_t& r0, uint32_t& r1,
                                      uint32_t& r2, uint32_t& r3,
                                      const void* p) {
    uint32_t a = smem_cast(p);
    asm volatile("ldmatrix.sync.aligned.m8n8.x4.shared.b16 {%0,%1,%2,%3},[%4];"
                 : "=r"(r0), "=r"(r1), "=r"(r2), "=r"(r3) : "r"(a));
}
__device__ __forceinline__ void ldsm4t(uint32_t& r0, uint32_t& r1,
                                       uint32_t& r2, uint32_t& r3,
                                       const void* p) {
    uint32_t a = smem_cast(p);
    asm volatile("ldmatrix.sync.aligned.m8n8.x4.trans.shared.b16 {%0,%1,%2,%3},[%4];"
                 : "=r"(r0), "=r"(r1), "=r"(r2), "=r"(r3) : "r"(a));
}

// m16n8k16 bf16 MMA, fp32 accumulate
__device__ __forceinline__ void mma16816(float* c, const uint32_t* a,
                                         uint32_t b0, uint32_t b1) {
    asm volatile(
        "mma.sync.aligned.m16n8k16.row.col.f32.bf16.bf16.f32 "
        "{%0,%1,%2,%3}, {%4,%5,%6,%7}, {%8,%9}, {%0,%1,%2,%3};\n"
        : "+f"(c[0]), "+f"(c[1]), "+f"(c[2]), "+f"(c[3])
        : "r"(a[0]), "r"(a[1]), "r"(a[2]), "r"(a[3]), "r"(b0), "r"(b1));
}

// ---------------------------------------------------------------------------
// Pre-kernels
// ---------------------------------------------------------------------------
__global__ __launch_bounds__(256)
void ln_stats_kernel(const float* __restrict__ x, float* mu, float* rs) {
    size_t row = blockIdx.x;
    float4 v = reinterpret_cast<const float4*>(x + row * Cc)[threadIdx.x];
    float s  = v.x + v.y + v.z + v.w;
    float sq = v.x*v.x + v.y*v.y + v.z*v.z + v.w*v.w;
    float2 r = block_reduce2(s, sq);
    if (threadIdx.x == 0) {
        float mean = r.x * (1.f / Cc);
        float var  = r.y * (1.f / Cc) - mean * mean;
        mu[row] = mean;
        rs[row] = rsqrtf(var + EPSv);
    }
}

__global__ __launch_bounds__(256)
void sred_kernel(const float* mu, const float* rs, float* S) {
    int b = blockIdx.x;
    float a = 0.f;
    for (int t = threadIdx.x; t < Tt; t += 256)
        a += mu[b * Tt + t] * rs[b * Tt + t];
    float2 r = block_reduce2(a, 0.f);
    if (threadIdx.x == 0) S[b] = r.x * (1.f / Tt);
}

__global__ __launch_bounds__(256)
void pooled_part_kernel(const float* __restrict__ x, const float* rs,
                        float* partial) {
    int b = blockIdx.y, sp = blockIdx.x;
    int t0 = sp * (Tt / NSP);
    __shared__ float srs[Tt / NSP];
    for (int i = threadIdx.x; i < Tt / NSP; i += 256) srs[i] = rs[b * Tt + t0 + i];
    __syncthreads();
    int c = threadIdx.x * 4;
    float4 acc = make_float4(0.f, 0.f, 0.f, 0.f);
    for (int r = 0; r < Tt / NSP; r++) {
        float4 v = *reinterpret_cast<const float4*>(
            &x[((size_t)b * Tt + t0 + r) * Cc + c]);
        float w = srs[r];
        acc.x = fmaf(v.x, w, acc.x);
        acc.y = fmaf(v.y, w, acc.y);
        acc.z = fmaf(v.z, w, acc.z);
        acc.w = fmaf(v.w, w, acc.w);
    }
    *reinterpret_cast<float4*>(&partial[((size_t)b * NSP + sp) * Cc + c]) = acc;
}

__global__ __launch_bounds__(256)
void pooled_reduce_kernel(const float* partial, const float* S,
                          const float* __restrict__ lnw,
                          const float* __restrict__ lnb,
                          float* pooled) {
    int idx = blockIdx.x * 256 + threadIdx.x;
    int b = idx / Cc, c = idx % Cc;
    float a = 0.f;
    #pragma unroll
    for (int sp = 0; sp < NSP; sp++)
        a += partial[((size_t)b * NSP + sp) * Cc + c];
    pooled[idx] = lnw[c] * (a * (1.f / Tt) - S[b]) + lnb[c];
}

__global__ __launch_bounds__(256)
void gctx_kernel(const float* pooled,
                 const float* __restrict__ W,
                 const float* __restrict__ bias,
                 float* gctx) {
    int b  = blockIdx.x >> 4;
    int cb = blockIdx.x & 15;
    __shared__ float pb[Cc];
    __shared__ float red[256];
    for (int i = threadIdx.x; i < Cc; i += 256) pb[i] = pooled[b * Cc + i];
    __syncthreads();
    int o = threadIdx.x >> 2, ks = threadIdx.x & 3;
    int c = cb * 64 + o;
    float a = 0.f;
    int k0 = ks * 256;
    #pragma unroll 4
    for (int k = k0; k < k0 + 256; k++)
        a = fmaf(pb[k], W[(size_t)k * Cc + c], a);
    red[threadIdx.x] = a;
    __syncthreads();
    if (ks == 0) {
        float t = red[o*4] + red[o*4+1] + red[o*4+2] + red[o*4+3] + bias[c];
        gctx[b * Cc + c] = 1.f / (1.f + expf(-t));
    }
}

__device__ __forceinline__ float freq_mask_val(int f, int cut) {
    float mask = 1.f;
    if (cut < FB) {
        int tr = cut < 16 ? cut : 16;
        if (f >= cut) mask = 0.f;
        else if (tr > 0 && f >= cut - tr) {
            int i = f - (cut - tr);
            float tt = (tr > 1) ? (float)i / (float)(tr - 1) : 0.f;
            mask = 0.5f * (1.f + cospif(tt));
        }
    }
    return mask;
}

__global__ __launch_bounds__(256)
void freq_kernel(const float* __restrict__ kern,
                 const float* __restrict__ logits,
                 const int* __restrict__ cutp,
                 float* Wre, float* Wim) {
    __shared__ float ks[Kk];
    for (int i = threadIdx.x; i < Kk; i += 256) ks[i] = kern[i];
    __syncthreads();
    int f = blockIdx.x * 256 + threadIdx.x;
    if (f >= FB) return;
    float dc, ds;
    sincospif((float)f * (1.f / (NFFT / 2)), &ds, &dc);
    float re = 0.f, im = 0.f;
    for (int k0 = 0; k0 < Kk; k0 += 64) {
        int p = (f * k0) & (NFFT - 1);
        float c, sv;
        sincospif((float)p * (1.f / (NFFT / 2)), &sv, &c);
        #pragma unroll
        for (int k = k0; k < k0 + 64; k++) {
            float kv = ks[k];
            re = fmaf(kv,  c, re);
            im = fmaf(kv, -sv, im);
            float c2 = c * dc - sv * ds;
            sv = sv * dc + c * ds;
            c = c2;
        }
    }
    float g = 1.f / (1.f + expf(-logits[f]));
    float mask = freq_mask_val(f, *cutp);
    float coef = ((f == 0) || (f == NFFT / 2)) ? (1.f / NFFT) : (2.f / NFFT);
    float wgt = g * mask * coef;
    Wre[f] = re * wgt;
    Wim[f] = im * wgt;
}

__global__ __launch_bounds__(256)
void hfilt_kernel(const float* Wre, const float* Wim, float* h, float* flagp) {
    if (blockIdx.x == 0 && threadIdx.x == 0)
        *reinterpret_cast<int*>(flagp) = 0;
    __shared__ float sr[512], si[512];
    int s = blockIdx.x * 256 + threadIdx.x;
    float dc, dsn;
    sincospif((float)s * (1.f / (NFFT / 2)), &dsn, &dc);
    float acc = 0.f;
    for (int f0 = 0; f0 < FB; f0 += 512) {
        int n = min(512, FB - f0);
        __syncthreads();
        for (int i = threadIdx.x; i < n; i += 256) { sr[i] = Wre[f0 + i]; si[i] = Wim[f0 + i]; }
        __syncthreads();
        for (int ii = 0; ii < n; ii += 64) {
            int p = ((f0 + ii) * s) & (NFFT - 1);
            float c, sv;
            sincospif((float)p * (1.f / (NFFT / 2)), &sv, &c);
            int lim = min(ii + 64, n);
            #pragma unroll 4
            for (int i = ii; i < lim; i++) {
                acc = fmaf(sr[i],  c, acc);
                acc = fmaf(-si[i], sv, acc);
                float c2 = c * dc - sv * dsn;
                sv = sv * dc + c * dsn;
                c = c2;
            }
        }
    }
    h[s] = acc;
}

// ---------------------------------------------------------------------------
// Conv tile via bf16 MMA + ldmatrix, DOUBLE-BUFFERED K pipeline.
// Tile 128(t)x128(c), K-chunk 64. As [128][64] stride 72; Bs [64][128]
// stride 136. Stage(i+1) overlaps MMA(i); one sync per chunk.
// ---------------------------------------------------------------------------
#define AS_HS 72
#define BS_HS 136
#define ASZ (128*AS_HS)
#define BSZ (64*BS_HS)

__device__ __forceinline__ void conv_stage(const float* __restrict__ xb,
                                           const float* sh_h,
                                           const float* muArr, const float* rsArr,
                                           const float* wsh, const float* bsh,
                                           int t0, int c0, int k0,
                                           __nv_bfloat16* Asb, __nv_bfloat16* Bsb,
                                           int tid) {
    #pragma unroll
    for (int l = 0; l < 4; l++) {
        int i = tid + l * 256;
        int m = i >> 3, k8 = (i & 7) * 8;
        int base = t0 + m - k0 - k8;
        uint4 v;
        v.x = pack_bf2(sh_h[(base    ) & (NFFT-1)], sh_h[(base - 1) & (NFFT-1)]);
        v.y = pack_bf2(sh_h[(base - 2) & (NFFT-1)], sh_h[(base - 3) & (NFFT-1)]);
        v.z = pack_bf2(sh_h[(base - 4) & (NFFT-1)], sh_h[(base - 5) & (NFFT-1)]);
        v.w = pack_bf2(sh_h[(base - 6) & (NFFT-1)], sh_h[(base - 7) & (NFFT-1)]);
        *reinterpret_cast<uint4*>(&Asb[m * AS_HS + k8]) = v;
    }
    #pragma unroll
    for (int l = 0; l < 8; l++) {
        int i = tid + l * 256;
        int u = i >> 5, cb = (i & 31) * 4;
        int ug = k0 + u;
        float rstd = rsArr[ug];
        float nmu  = -muArr[ug] * rstd;
        float4 xv = *reinterpret_cast<const float4*>(&xb[(size_t)ug * Cc + c0 + cb]);
        float v0 = fmaf(xv.x, rstd, nmu) * wsh[cb]     + bsh[cb];
        float v1 = fmaf(xv.y, rstd, nmu) * wsh[cb + 1] + bsh[cb + 1];
        float v2 = fmaf(xv.z, rstd, nmu) * wsh[cb + 2] + bsh[cb + 2];
        float v3 = fmaf(xv.w, rstd, nmu) * wsh[cb + 3] + bsh[cb + 3];
        uint2 pk;
        pk.x = pack_bf2(v0, v1);
        pk.y = pack_bf2(v2, v3);
        *reinterpret_cast<uint2*>(&Bsb[u * BS_HS + cb]) = pk;
    }
}

__device__ void conv_tile_mma(const float* __restrict__ x, float* out,
                              int b, int t0, int c0,
                              const float* sh_h,
                              const float* muArr, const float* rsArr,
                              const float* wsh, const float* bsh,
                              const float* __restrict__ gain,
                              const float* gctx_b,
                              __nv_bfloat16* As, __nv_bfloat16* Bs,
                              int tid) {
    const int lane = tid & 31, wid = tid >> 5;
    const int warp_m = wid & 3, warp_n = wid >> 2;
    const int bm = warp_m * 32, bn = warp_n * 64;
    const int r = lane >> 2, cq = lane & 3;
    const float* xb = x + (size_t)b * Tt * Cc;
    const int a_row = (lane & 15), a_koff = (lane >> 4) * 8;
    const int b_krow = (lane & 7) + ((lane >> 3) & 1) * 8;
    const int b_noff = (lane >> 4) * 8;

    float acc[2][8][4];
    #pragma unroll
    for (int mt = 0; mt < 2; mt++)
        #pragma unroll
        for (int nt = 0; nt < 8; nt++)
            #pragma unroll
            for (int j = 0; j < 4; j++) acc[mt][nt][j] = 0.f;

    conv_stage(xb, sh_h, muArr, rsArr, wsh, bsh, t0, c0, 0, As, Bs, tid);
    __syncthreads();

    const int NCHUNK = Tt / 64;
    for (int ic = 0; ic < NCHUNK; ic++) {
        if (ic + 1 < NCHUNK)
            conv_stage(xb, sh_h, muArr, rsArr, wsh, bsh, t0, c0, (ic + 1) * 64,
                       As + ((ic + 1) & 1) * ASZ, Bs + ((ic + 1) & 1) * BSZ, tid);
        const __nv_bfloat16* Ac = As + (ic & 1) * ASZ;
        const __nv_bfloat16* Bc = Bs + (ic & 1) * BSZ;
        #pragma unroll
        for (int s = 0; s < 4; s++) {
            int kk16 = s * 16;
            uint32_t a[2][4];
            #pragma unroll
            for (int mt = 0; mt < 2; mt++)
                ldsm4(a[mt][0], a[mt][1], a[mt][2], a[mt][3],
                      &Ac[(bm + mt * 16 + a_row) * AS_HS + kk16 + a_koff]);
            #pragma unroll
            for (int q = 0; q < 4; q++) {
                uint32_t t0r, t1r, t2r, t3r;
                ldsm4t(t0r, t1r, t2r, t3r,
                       &Bc[(kk16 + b_krow) * BS_HS + bn + q * 16 + b_noff]);
                mma16816(acc[0][2*q],   a[0], t0r, t1r);
                mma16816(acc[0][2*q+1], a[0], t2r, t3r);
                mma16816(acc[1][2*q],   a[1], t0r, t1r);
                mma16816(acc[1][2*q+1], a[1], t2r, t3r);
            }
        }
        __syncthreads();
    }

    // epilogue: x2 = x + acc*gain*gctx
    #pragma unroll
    for (int mt = 0; mt < 2; mt++) {
        #pragma unroll
        for (int nt = 0; nt < 8; nt++) {
            int t = t0 + bm + mt * 16 + r;
            int c = c0 + bn + nt * 8 + cq * 2;
            float s0 = gain[c]     * gctx_b[c];
            float s1 = gain[c + 1] * gctx_b[c + 1];
            size_t ro = ((size_t)b * Tt + t) * Cc + c;
            float2 xr0 = *reinterpret_cast<const float2*>(&x[ro]);
            float2 o0;
            o0.x = xr0.x + acc[mt][nt][0] * s0;
            o0.y = xr0.y + acc[mt][nt][1] * s1;
            *reinterpret_cast<float2*>(&out[ro]) = o0;
            float2 xr1 = *reinterpret_cast<const float2*>(&x[ro + 8 * Cc]);
            float2 o1;
            o1.x = xr1.x + acc[mt][nt][2] * s0;
            o1.y = xr1.y + acc[mt][nt][3] * s1;
            *reinterpret_cast<float2*>(&out[ro + 8 * Cc]) = o1;
        }
    }
}

#define CONV_SMEM (32768 + 2*ASZ*2 + 2*BSZ*2)   // 32768+36864+34816 = 104448

__global__ __launch_bounds__(256)
void conv_pass1_kernel(const float* __restrict__ x,
                       const float* __restrict__ lnw,
                       const float* __restrict__ lnb,
                       const float* __restrict__ gain,
                       float* out) {
    int b = blockIdx.z;
    if (b == 0 && blockIdx.y == 0) return;           // scratch tile -> fixup
    int t0 = blockIdx.y * 128;
    int c0 = blockIdx.x * 128;
    extern __shared__ char sm[];
    float* sh_h = reinterpret_cast<float*>(sm);
    __nv_bfloat16* As = reinterpret_cast<__nv_bfloat16*>(sm + 32768);
    __nv_bfloat16* Bs = reinterpret_cast<__nv_bfloat16*>(sm + 32768 + 2*ASZ*2);
    __shared__ float wsh[128], bsh[128];
    int tid = threadIdx.x;
    const float* hG = out + OFF_H;
    for (int i = tid * 4; i < NFFT; i += 1024)
        *reinterpret_cast<float4*>(&sh_h[i]) = *reinterpret_cast<const float4*>(&hG[i]);
    if (tid < 128) { wsh[tid] = lnw[c0 + tid]; bsh[tid] = lnb[c0 + tid]; }
    __syncthreads();
    conv_tile_mma(x, out, b, t0, c0, sh_h,
                  out + OFF_MU + (size_t)b * Tt, out + OFF_RS + (size_t)b * Tt,
                  wsh, bsh, gain, out + OFF_GC + (size_t)b * Cc, As, Bs, tid);
}

#define FIXUP_SMEM (32768 + 16384 + 16384 + 2*ASZ*2 + 2*BSZ*2)  // 137216

__global__ __launch_bounds__(256)
void conv_fixup_kernel(const float* __restrict__ x,
                       const float* __restrict__ lnw,
                       const float* __restrict__ lnb,
                       const float* __restrict__ gain,
                       float* out) {
    extern __shared__ char sm[];
    float* sh_h = reinterpret_cast<float*>(sm);
    float* smu  = reinterpret_cast<float*>(sm + 32768);
    float* srs  = reinterpret_cast<float*>(sm + 49152);
    __nv_bfloat16* As = reinterpret_cast<__nv_bfloat16*>(sm + 65536);
    __nv_bfloat16* Bs = reinterpret_cast<__nv_bfloat16*>(sm + 65536 + 2*ASZ*2);
    __shared__ float wsh[128], bsh[128], sgc[128];
    int tid = threadIdx.x;
    int c0 = blockIdx.x * 128;

    for (int i = tid; i < NFFT; i += 256) sh_h[i] = out[OFF_H + i];
    for (int i = tid; i < Tt; i += 256) {
        smu[i] = out[OFF_MU + i];
        srs[i] = out[OFF_RS + i];
    }
    if (tid < 128) {
        sgc[tid] = out[OFF_GC + c0 + tid];
        wsh[tid] = lnw[c0 + tid];
        bsh[tid] = lnb[c0 + tid];
    }
    __syncthreads();
    if (tid == 0) {       // all 8 co-resident blocks done copying scratch
        int* flag = reinterpret_cast<int*>(&out[OFF_FLAG]);
        atomicAdd(flag, 1);
        while (*reinterpret_cast<volatile int*>(flag) < 8) { }
    }
    __syncthreads();

    conv_tile_mma(x, out, 0, 0, c0, sh_h, smu, srs,
                  wsh, bsh, gain, sgc - c0, As, Bs, tid);
}

// ---------------------------------------------------------------------------
// Fused FFN via bf16 MMA + ldmatrix, DOUBLE-BUFFERED weight pipeline.
// Block = 64 rows, 8 warps (2x4). Weight chunk K=32 (two buffers).
// sf [64][1024] stride 1032 (A); sht [64][256] stride 264; wst [32][256]
// stride 264 x2 buffers.
// ---------------------------------------------------------------------------
#define MT 64
#define SF_HS  1032
#define SHT_HS 264
#define WST_HS 264
#define WSZ (32*WST_HS)
#define FFN_SMEM (MT*SF_HS*2 + MT*SHT_HS*2 + 2*WSZ*2)   // 132096+33792+33792

__device__ __forceinline__ void ffn_stage_w(const float* __restrict__ W,
                                            size_t ldw, size_t krow0, int col0,
                                            __nv_bfloat16* wstb, int tid) {
    #pragma unroll
    for (int l = 0; l < 8; l++) {
        int i = tid + l * 256;
        int k = i >> 6, cb = (i & 63) * 4;
        float4 wv = *reinterpret_cast<const float4*>(&W[(krow0 + k) * ldw + col0 + cb]);
        uint2 pk;
        pk.x = pack_bf2(wv.x, wv.y);
        pk.y = pack_bf2(wv.z, wv.w);
        *reinterpret_cast<uint2*>(&wstb[k * WST_HS + cb]) = pk;
    }
}

__global__ __launch_bounds__(256)
void ffn_kernel(float* out,
                const float* __restrict__ flnw, const float* __restrict__ flnb,
                const float* __restrict__ w1, const float* __restrict__ b1,
                const float* __restrict__ w2, const float* __restrict__ b2) {
    extern __shared__ char sm[];
    __nv_bfloat16* sf  = reinterpret_cast<__nv_bfloat16*>(sm);
    __nv_bfloat16* sht = reinterpret_cast<__nv_bfloat16*>(sm + MT*SF_HS*2);
    __nv_bfloat16* wst = reinterpret_cast<__nv_bfloat16*>(sm + MT*SF_HS*2 + MT*SHT_HS*2);
    __shared__ float smu[MT], srs[MT];

    int tid = threadIdx.x;
    size_t r0 = (size_t)blockIdx.x * MT;
    int lane = tid & 31, wid = tid >> 5;
    int warp_m = wid & 1, warp_n = wid >> 1;
    int bm = warp_m * 32, bn = warp_n * 64;
    int r = lane >> 2, cq = lane & 3;
    const int a_row = (lane & 15), a_koff = (lane >> 4) * 8;
    const int b_krow = (lane & 7) + ((lane >> 3) & 1) * 8;
    const int b_noff = (lane >> 4) * 8;

    // LN2 stats (warp per row)
    for (int rr = wid; rr < MT; rr += 8) {
        const float* row = out + (r0 + rr) * Cc;
        float s = 0.f, q = 0.f;
        for (int i = lane; i < Cc; i += 32) { float v = row[i]; s += v; q = fmaf(v, v, q); }
        for (int o = 16; o > 0; o >>= 1) {
            s += __shfl_xor_sync(0xFFFFFFFFu, s, o);
            q += __shfl_xor_sync(0xFFFFFFFFu, q, o);
        }
        if (lane == 0) {
            float m = s * (1.f / Cc);
            smu[rr] = m;
            srs[rr] = rsqrtf(q * (1.f / Cc) - m * m + EPSv);
        }
    }
    __syncthreads();

    // stage sf = LN(x2) bf16
    for (int i = tid * 4; i < MT * Cc; i += 1024) {
        int row = i >> 10, col = i & 1023;
        float4 v = *reinterpret_cast<const float4*>(&out[(r0 + row) * Cc + col]);
        float rs = srs[row];
        float nmu = -smu[row] * rs;
        float4 wv = *reinterpret_cast<const float4*>(&flnw[col]);
        float4 bv = *reinterpret_cast<const float4*>(&flnb[col]);
        uint2 pk;
        pk.x = pack_bf2(fmaf(v.x, rs, nmu) * wv.x + bv.x, fmaf(v.y, rs, nmu) * wv.y + bv.y);
        pk.y = pack_bf2(fmaf(v.z, rs, nmu) * wv.z + bv.z, fmaf(v.w, rs, nmu) * wv.w + bv.w);
        *reinterpret_cast<uint2*>(&sf[row * SF_HS + col]) = pk;
    }
    __syncthreads();

    for (int hc = 0; hc < Hh; hc += 256) {
        // ---- GEMM1: sht[64,256] = gelu(sf @ w1[:,hc:hc+256] + b1) ----
        float acc[2][8][4];
        #pragma unroll
        for (int mt = 0; mt < 2; mt++)
            #pragma unroll
            for (int nt = 0; nt < 8; nt++)
                #pragma unroll
                for (int j = 0; j < 4; j++) acc[mt][nt][j] = 0.f;

        ffn_stage_w(w1, Hh, 0, hc, wst, tid);
        __syncthreads();
        const int NC1 = Cc / 32;
        for (int ic = 0; ic < NC1; ic++) {
            if (ic + 1 < NC1)
                ffn_stage_w(w1, Hh, (size_t)(ic + 1) * 32, hc,
                            wst + ((ic + 1) & 1) * WSZ, tid);
            const __nv_bfloat16* wc = wst + (ic & 1) * WSZ;
            int kg = ic * 32;
            #pragma unroll
            for (int s = 0; s < 2; s++) {
                int kk16 = s * 16;
                uint32_t a[2][4];
                #pragma unroll
                for (int mt = 0; mt < 2; mt++)
                    ldsm4(a[mt][0], a[mt][1], a[mt][2], a[mt][3],
                          &sf[(bm + mt * 16 + a_row) * SF_HS + kg + kk16 + a_koff]);
                #pragma unroll
                for (int q = 0; q < 4; q++) {
                    uint32_t t0r, t1r, t2r, t3r;
                    ldsm4t(t0r, t1r, t2r, t3r,
                           &wc[(kk16 + b_krow) * WST_HS + bn + q * 16 + b_noff]);
                    mma16816(acc[0][2*q],   a[0], t0r, t1r);
                    mma16816(acc[0][2*q+1], a[0], t2r, t3r);
                    mma16816(acc[1][2*q],   a[1], t0r, t1r);
                    mma16816(acc[1][2*q+1], a[1], t2r, t3r);
                }
            }
            __syncthreads();
        }
        // epilogue1: bias + gelu -> sht
        #pragma unroll
        for (int mt = 0; mt < 2; mt++) {
            #pragma unroll
            for (int nt = 0; nt < 8; nt++) {
                int row = bm + mt * 16 + r;
                int col = bn + nt * 8 + cq * 2;
                float bb0 = b1[hc + col], bb1 = b1[hc + col + 1];
                float v0 = acc[mt][nt][0] + bb0;
                float v1 = acc[mt][nt][1] + bb1;
                float v2 = acc[mt][nt][2] + bb0;
                float v3 = acc[mt][nt][3] + bb1;
                v0 = 0.5f * v0 * (1.f + erff(v0 * 0.70710678118654752f));
                v1 = 0.5f * v1 * (1.f + erff(v1 * 0.70710678118654752f));
                v2 = 0.5f * v2 * (1.f + erff(v2 * 0.70710678118654752f));
                v3 = 0.5f * v3 * (1.f + erff(v3 * 0.70710678118654752f));
                *reinterpret_cast<uint32_t*>(&sht[row * SHT_HS + col])       = pack_bf2(v0, v1);
                *reinterpret_cast<uint32_t*>(&sht[(row + 8) * SHT_HS + col]) = pack_bf2(v2, v3);
            }
        }
        __syncthreads();

        // ---- GEMM2: out[64,:] += sht @ w2[hc:hc+256,:] (+ b2 on hc==0) ----
        for (int cc0 = 0; cc0 < Cc; cc0 += 256) {
            float acc2[2][8][4];
            #pragma unroll
            for (int mt = 0; mt < 2; mt++)
                #pragma unroll
                for (int nt = 0; nt < 8; nt++)
                    #pragma unroll
                    for (int j = 0; j < 4; j++) acc2[mt][nt][j] = 0.f;

            ffn_stage_w(w2, Cc, (size_t)hc, cc0, wst, tid);
            __syncthreads();
            const int NC2 = 256 / 32;
            for (int ic = 0; ic < NC2; ic++) {
                if (ic + 1 < NC2)
                    ffn_stage_w(w2, Cc, (size_t)hc + (ic + 1) * 32, cc0,
                                wst + ((ic + 1) & 1) * WSZ, tid);
                const __nv_bfloat16* wc = wst + (ic & 1) * WSZ;
                int kg = ic * 32;
                #pragma unroll
                for (int s = 0; s < 2; s++) {
                    int kk16 = s * 16;
                    uint32_t a[2][4];
                    #pragma unroll
                    for (int mt = 0; mt < 2; mt++)
                        ldsm4(a[mt][0], a[mt][1], a[mt][2], a[mt][3],
                              &sht[(bm + mt * 16 + a_row) * SHT_HS + kg + kk16 + a_koff]);
                    #pragma unroll
                    for (int q = 0; q < 4; q++) {
                        uint32_t t0r, t1r, t2r, t3r;
                        ldsm4t(t0r, t1r, t2r, t3r,
                               &wc[(kk16 + b_krow) * WST_HS + bn + q * 16 + b_noff]);
                        mma16816(acc2[0][2*q],   a[0], t0r, t1r);
                        mma16816(acc2[0][2*q+1], a[0], t2r, t3r);
                        mma16816(acc2[1][2*q],   a[1], t0r, t1r);
                        mma16816(acc2[1][2*q+1], a[1], t2r, t3r);
                    }
                }
                __syncthreads();
            }
            // thread-private RMW into out (deterministic ownership)
            #pragma unroll
            for (int mt = 0; mt < 2; mt++) {
                #pragma unroll
                for (int nt = 0; nt < 8; nt++) {
                    int row = bm + mt * 16 + r;
                    int col = cc0 + bn + nt * 8 + cq * 2;
                    size_t ro = (r0 + row) * Cc + col;
                    float2 o0 = *reinterpret_cast<const float2*>(&out[ro]);
                    float2 o1 = *reinterpret_cast<const float2*>(&out[ro + 8 * Cc]);
                    if (hc == 0) {
                        float bb0 = b2[col], bb1 = b2[col + 1];
                        o0.x += bb0; o0.y += bb1;
                        o1.x += bb0; o1.y += bb1;
                    }
                    o0.x += acc2[mt][nt][0]; o0.y += acc2[mt][nt][1];
                    o1.x += acc2[mt][nt][2]; o1.y += acc2[mt][nt][3];
                    *reinterpret_cast<float2*>(&out[ro]) = o0;
                    *reinterpret_cast<float2*>(&out[ro + 8 * Cc]) = o1;
                }
            }
        }
        __syncthreads();
    }
}

// ---------------------------------------------------------------------------
// kernel_launch
// ---------------------------------------------------------------------------
extern "C" void kernel_launch(void* const* d_in, const int* in_sizes, int n_in,
                              void* d_out, int out_size) {
    const float* x    = (const float*)d_in[0];
    const float* kern = (const float*)d_in[1];
    const float* gain = (const float*)d_in[2];
    const float* gfl  = (const float*)d_in[3];
    const float* gcw  = (const float*)d_in[4];
    const float* gcb  = (const float*)d_in[5];
    const float* lnw  = (const float*)d_in[6];
    const float* lnb  = (const float*)d_in[7];
    const float* flnw = (const float*)d_in[8];
    const float* flnb = (const float*)d_in[9];
    const float* w1   = (const float*)d_in[10];
    const float* b1   = (const float*)d_in[11];
    const float* w2   = (const float*)d_in[12];
    const float* b2   = (const float*)d_in[13];
    const int*   cut  = (const int*)d_in[14];
    float* out = (float*)d_out;

    cudaFuncSetAttribute(conv_pass1_kernel,
                         cudaFuncAttributeMaxDynamicSharedMemorySize, CONV_SMEM);
    cudaFuncSetAttribute(conv_fixup_kernel,
                         cudaFuncAttributeMaxDynamicSharedMemorySize, FIXUP_SMEM);
    cudaFuncSetAttribute(ffn_kernel,
                         cudaFuncAttributeMaxDynamicSharedMemorySize, FFN_SMEM);

    ln_stats_kernel<<<NROWS, 256>>>(x, out + OFF_MU, out + OFF_RS);
    sred_kernel<<<Bb, 256>>>(out + OFF_MU, out + OFF_RS, out + OFF_S);
    pooled_part_kernel<<<dim3(NSP, Bb), 256>>>(x, out + OFF_RS, out + OFF_PP);
    pooled_reduce_kernel<<<(Bb * Cc) / 256, 256>>>(out + OFF_PP, out + OFF_S,
                                                   lnw, lnb, out + OFF_PL);
    gctx_kernel<<<Bb * (Cc / 64), 256>>>(out + OFF_PL, gcw, gcb, out + OFF_GC);
    freq_kernel<<<(FB + 255) / 256, 256>>>(kern, gfl, cut, out + OFF_WRE, out + OFF_WIM);
    hfilt_kernel<<<NFFT / 256, 256>>>(out + OFF_WRE, out + OFF_WIM,
                                      out + OFF_H, out + OFF_FLAG);
    conv_pass1_kernel<<<dim3(Cc / 128, Tt / 128, Bb), 256, CONV_SMEM>>>(
        x, lnw, lnb, gain, out);
    conv_fixup_kernel<<<8, 256, FIXUP_SMEM>>>(x, lnw, lnb, gain, out);
    ffn_kernel<<<NROWS / MT, 256, FFN_SMEM>>>(out, flnw, flnb, w1, b1, w2, b2);
}

// round 14
// speedup vs baseline: 1.0501x; 1.0501x over previous
#include <cuda_runtime.h>
#include <cuda_bf16.h>
#include <math.h>
#include <stdint.h>

// ---------------------------------------------------------------------------
// Problem constants (FixedSpectralBlock: B=4, T=4096, C=1024, K=1024)
// ---------------------------------------------------------------------------
#define Bb   4
#define Tt   4096
#define Cc   1024
#define Kk   1024
#define NFFT 8192
#define FB   4097          // NFFT/2 + 1
#define Hh   2048          // 2*C
#define EPSv 1e-5f
#define NROWS (Bb*Tt)
#define NSP  16            // pooled T-splits

// Scratch layout inside d_out rows 0..127 of batch 0 (conv pass-1 skips that
// tile; fixup reads scratch then overwrites it). Offsets in floats:
#define OFF_H    0        // hfilt          [8192]
#define OFF_WRE  8192     // W.re           [4160]
#define OFF_WIM  12352    // W.im           [4160]
#define OFF_MU   16512    // LN1 mean       [16384]
#define OFF_RS   32896    // LN1 rstd       [16384]
#define OFF_S    49280    // per-batch S    [8]
#define OFF_PL   49288    // pooled         [4096]
#define OFF_GC   53384    // gctx           [4096]
#define OFF_FLAG 58368    // fixup spin-barrier flag
#define OFF_PP   58376    // pooled partials [Bb*NSP*Cc = 65536] (end 123912)

// ---------------------------------------------------------------------------
// Helpers
// ---------------------------------------------------------------------------
__device__ __forceinline__ float2 block_reduce2(float a, float b) {
    __shared__ float sa[8], sb[8];
    for (int o = 16; o > 0; o >>= 1) {
        a += __shfl_xor_sync(0xFFFFFFFFu, a, o);
        b += __shfl_xor_sync(0xFFFFFFFFu, b, o);
    }
    int w = threadIdx.x >> 5, l = threadIdx.x & 31;
    if (l == 0) { sa[w] = a; sb[w] = b; }
    __syncthreads();
    if (w == 0) {
        a = (l < 8) ? sa[l] : 0.f;
        b = (l < 8) ? sb[l] : 0.f;
        for (int o = 4; o > 0; o >>= 1) {
            a += __shfl_xor_sync(0xFFFFFFFFu, a, o);
            b += __shfl_xor_sync(0xFFFFFFFFu, b, o);
        }
        if (l == 0) { sa[0] = a; sb[0] = b; }
    }
    __syncthreads();
    return make_float2(sa[0], sb[0]);
}

__device__ __forceinline__ uint32_t pack_bf2(float lo, float hi) {
    __nv_bfloat162 h = __floats2bfloat162_rn(lo, hi);
    return *reinterpret_cast<uint32_t*>(&h);
}

__device__ __forceinline__ uint32_t smem_cast(const void* p) {
    return (uint32_t)__cvta_generic_to_shared(p);
}

__device__ __forceinline__ void ldsm4(uint32_t& r0, uint32_t& r1,
                                      uint32_t& r2, uint32_t& r3,
                                      const void* p) {
    uint32_t a = smem_cast(p);
    asm volatile("ldmatrix.sync.aligned.m8n8.x4.shared.b16 {%0,%1,%2,%3},[%4];"
                 : "=r"(r0), "=r"(r1), "=r"(r2), "=r"(r3) : "r"(a));
}
__device__ __forceinline__ void ldsm4t(uint32_t& r0, uint32_t& r1,
                                       uint32_t& r2, uint32_t& r3,
                                       const void* p) {
    uint32_t a = smem_cast(p);
    asm volatile("ldmatrix.sync.aligned.m8n8.x4.trans.shared.b16 {%0,%1,%2,%3},[%4];"
                 : "=r"(r0), "=r"(r1), "=r"(r2), "=r"(r3) : "r"(a));
}

// m16n8k16 bf16 MMA, fp32 accumulate
__device__ __forceinline__ void mma16816(float* c, const uint32_t* a,
                                         uint32_t b0, uint32_t b1) {
    asm volatile(
        "mma.sync.aligned.m16n8k16.row.col.f32.bf16.bf16.f32 "
        "{%0,%1,%2,%3}, {%4,%5,%6,%7}, {%8,%9}, {%0,%1,%2,%3};\n"
        : "+f"(c[0]), "+f"(c[1]), "+f"(c[2]), "+f"(c[3])
        : "r"(a[0]), "r"(a[1]), "r"(a[2]), "r"(a[3]), "r"(b0), "r"(b1));
}

// ---------------------------------------------------------------------------
// Pre-kernels
// ---------------------------------------------------------------------------
__global__ __launch_bounds__(256)
void ln_stats_kernel(const float* __restrict__ x, float* mu, float* rs) {
    size_t row = blockIdx.x;
    float4 v = reinterpret_cast<const float4*>(x + row * Cc)[threadIdx.x];
    float s  = v.x + v.y + v.z + v.w;
    float sq = v.x*v.x + v.y*v.y + v.z*v.z + v.w*v.w;
    float2 r = block_reduce2(s, sq);
    if (threadIdx.x == 0) {
        float mean = r.x * (1.f / Cc);
        float var  = r.y * (1.f / Cc) - mean * mean;
        mu[row] = mean;
        rs[row] = rsqrtf(var + EPSv);
    }
}

__global__ __launch_bounds__(256)
void sred_kernel(const float* mu, const float* rs, float* S) {
    int b = blockIdx.x;
    float a = 0.f;
    for (int t = threadIdx.x; t < Tt; t += 256)
        a += mu[b * Tt + t] * rs[b * Tt + t];
    float2 r = block_reduce2(a, 0.f);
    if (threadIdx.x == 0) S[b] = r.x * (1.f / Tt);
}

__global__ __launch_bounds__(256)
void pooled_part_kernel(const float* __restrict__ x, const float* rs,
                        float* partial) {
    int b = blockIdx.y, sp = blockIdx.x;
    int t0 = sp * (Tt / NSP);
    __shared__ float srs[Tt / NSP];
    for (int i = threadIdx.x; i < Tt / NSP; i += 256) srs[i] = rs[b * Tt + t0 + i];
    __syncthreads();
    int c = threadIdx.x * 4;
    float4 acc = make_float4(0.f, 0.f, 0.f, 0.f);
    for (int r = 0; r < Tt / NSP; r++) {
        float4 v = *reinterpret_cast<const float4*>(
            &x[((size_t)b * Tt + t0 + r) * Cc + c]);
        float w = srs[r];
        acc.x = fmaf(v.x, w, acc.x);
        acc.y = fmaf(v.y, w, acc.y);
        acc.z = fmaf(v.z, w, acc.z);
        acc.w = fmaf(v.w, w, acc.w);
    }
    *reinterpret_cast<float4*>(&partial[((size_t)b * NSP + sp) * Cc + c]) = acc;
}

__global__ __launch_bounds__(256)
void pooled_reduce_kernel(const float* partial, const float* S,
                          const float* __restrict__ lnw,
                          const float* __restrict__ lnb,
                          float* pooled) {
    int idx = blockIdx.x * 256 + threadIdx.x;
    int b = idx / Cc, c = idx % Cc;
    float a = 0.f;
    #pragma unroll
    for (int sp = 0; sp < NSP; sp++)
        a += partial[((size_t)b * NSP + sp) * Cc + c];
    pooled[idx] = lnw[c] * (a * (1.f / Tt) - S[b]) + lnb[c];
}

__global__ __launch_bounds__(256)
void gctx_kernel(const float* pooled,
                 const float* __restrict__ W,
                 const float* __restrict__ bias,
                 float* gctx) {
    int b  = blockIdx.x >> 4;
    int cb = blockIdx.x & 15;
    __shared__ float pb[Cc];
    __shared__ float red[256];
    for (int i = threadIdx.x; i < Cc; i += 256) pb[i] = pooled[b * Cc + i];
    __syncthreads();
    int o = threadIdx.x >> 2, ks = threadIdx.x & 3;
    int c = cb * 64 + o;
    float a = 0.f;
    int k0 = ks * 256;
    #pragma unroll 4
    for (int k = k0; k < k0 + 256; k++)
        a = fmaf(pb[k], W[(size_t)k * Cc + c], a);
    red[threadIdx.x] = a;
    __syncthreads();
    if (ks == 0) {
        float t = red[o*4] + red[o*4+1] + red[o*4+2] + red[o*4+3] + bias[c];
        gctx[b * Cc + c] = 1.f / (1.f + expf(-t));
    }
}

__device__ __forceinline__ float freq_mask_val(int f, int cut) {
    float mask = 1.f;
    if (cut < FB) {
        int tr = cut < 16 ? cut : 16;
        if (f >= cut) mask = 0.f;
        else if (tr > 0 && f >= cut - tr) {
            int i = f - (cut - tr);
            float tt = (tr > 1) ? (float)i / (float)(tr - 1) : 0.f;
            mask = 0.5f * (1.f + cospif(tt));
        }
    }
    return mask;
}

__global__ __launch_bounds__(256)
void freq_kernel(const float* __restrict__ kern,
                 const float* __restrict__ logits,
                 const int* __restrict__ cutp,
                 float* Wre, float* Wim) {
    __shared__ float ks[Kk];
    for (int i = threadIdx.x; i < Kk; i += 256) ks[i] = kern[i];
    __syncthreads();
    int f = blockIdx.x * 256 + threadIdx.x;
    if (f >= FB) return;
    float dc, ds;
    sincospif((float)f * (1.f / (NFFT / 2)), &ds, &dc);
    float re = 0.f, im = 0.f;
    for (int k0 = 0; k0 < Kk; k0 += 64) {
        int p = (f * k0) & (NFFT - 1);
        float c, sv;
        sincospif((float)p * (1.f / (NFFT / 2)), &sv, &c);
        #pragma unroll
        for (int k = k0; k < k0 + 64; k++) {
            float kv = ks[k];
            re = fmaf(kv,  c, re);
            im = fmaf(kv, -sv, im);
            float c2 = c * dc - sv * ds;
            sv = sv * dc + c * ds;
            c = c2;
        }
    }
    float g = 1.f / (1.f + expf(-logits[f]));
    float mask = freq_mask_val(f, *cutp);
    float coef = ((f == 0) || (f == NFFT / 2)) ? (1.f / NFFT) : (2.f / NFFT);
    float wgt = g * mask * coef;
    Wre[f] = re * wgt;
    Wim[f] = im * wgt;
}

__global__ __launch_bounds__(256)
void hfilt_kernel(const float* Wre, const float* Wim, float* h, float* flagp) {
    if (blockIdx.x == 0 && threadIdx.x == 0)
        *reinterpret_cast<int*>(flagp) = 0;
    __shared__ float sr[512], si[512];
    int s = blockIdx.x * 256 + threadIdx.x;
    float dc, dsn;
    sincospif((float)s * (1.f / (NFFT / 2)), &dsn, &dc);
    float acc = 0.f;
    for (int f0 = 0; f0 < FB; f0 += 512) {
        int n = min(512, FB - f0);
        __syncthreads();
        for (int i = threadIdx.x; i < n; i += 256) { sr[i] = Wre[f0 + i]; si[i] = Wim[f0 + i]; }
        __syncthreads();
        for (int ii = 0; ii < n; ii += 64) {
            int p = ((f0 + ii) * s) & (NFFT - 1);
            float c, sv;
            sincospif((float)p * (1.f / (NFFT / 2)), &sv, &c);
            int lim = min(ii + 64, n);
            #pragma unroll 4
            for (int i = ii; i < lim; i++) {
                acc = fmaf(sr[i],  c, acc);
                acc = fmaf(-si[i], sv, acc);
                float c2 = c * dc - sv * dsn;
                sv = sv * dc + c * dsn;
                c = c2;
            }
        }
    }
    h[s] = acc;
}

// ---------------------------------------------------------------------------
// Conv tile via bf16 MMA + ldmatrix, WIDE tile: 128(t) x 256(c), K-chunk 64.
// As [128][64] stride 72; Bs [64][256] stride 264 (both ≡16B mod 128B).
// 8 warps: 4m x 2n, warp tile 32 x 128. acc[2][16][4] (128 fp32/thread).
// ---------------------------------------------------------------------------
#define AS_HS 72
#define BS_HS 264
#define CTN   256     // conv tile N (columns)

__device__ void conv_tile_mma(const float* __restrict__ x, float* out,
                              int b, int t0, int c0,
                              const float* sh_h,
                              const float* muArr, const float* rsArr,
                              const float* wsh, const float* bsh,
                              const float* __restrict__ gain,
                              const float* gctx_b,
                              __nv_bfloat16* As, __nv_bfloat16* Bs,
                              int tid) {
    const int lane = tid & 31, wid = tid >> 5;
    const int warp_m = wid & 3, warp_n = wid >> 2;
    const int bm = warp_m * 32, bn = warp_n * 128;
    const int r = lane >> 2, cq = lane & 3;
    const float* xb = x + (size_t)b * Tt * Cc;
    const int a_row = (lane & 15), a_koff = (lane >> 4) * 8;
    const int b_krow = (lane & 7) + ((lane >> 3) & 1) * 8;
    const int b_noff = (lane >> 4) * 8;

    float acc[2][16][4];
    #pragma unroll
    for (int mt = 0; mt < 2; mt++)
        #pragma unroll
        for (int nt = 0; nt < 16; nt++)
            #pragma unroll
            for (int j = 0; j < 4; j++) acc[mt][nt][j] = 0.f;

    for (int k0 = 0; k0 < Tt; k0 += 64) {
        // stage A: As[m][k] = h[(t0+m-k0-k)&8191]
        #pragma unroll
        for (int l = 0; l < 4; l++) {
            int i = tid + l * 256;
            int m = i >> 3, k8 = (i & 7) * 8;
            int base = t0 + m - k0 - k8;
            uint4 v;
            v.x = pack_bf2(sh_h[(base    ) & (NFFT-1)], sh_h[(base - 1) & (NFFT-1)]);
            v.y = pack_bf2(sh_h[(base - 2) & (NFFT-1)], sh_h[(base - 3) & (NFFT-1)]);
            v.z = pack_bf2(sh_h[(base - 4) & (NFFT-1)], sh_h[(base - 5) & (NFFT-1)]);
            v.w = pack_bf2(sh_h[(base - 6) & (NFFT-1)], sh_h[(base - 7) & (NFFT-1)]);
            *reinterpret_cast<uint4*>(&As[m * AS_HS + k8]) = v;
        }
        // stage B natural [k][n]: Bs[u][n] = LN(x)[k0+u][c0+n]
        #pragma unroll
        for (int l = 0; l < 16; l++) {
            int i = tid + l * 256;
            int u = i >> 6, cb = (i & 63) * 4;
            int ug = k0 + u;
            float rstd = rsArr[ug];
            float nmu  = -muArr[ug] * rstd;
            float4 xv = *reinterpret_cast<const float4*>(&xb[(size_t)ug * Cc + c0 + cb]);
            float v0 = fmaf(xv.x, rstd, nmu) * wsh[cb]     + bsh[cb];
            float v1 = fmaf(xv.y, rstd, nmu) * wsh[cb + 1] + bsh[cb + 1];
            float v2 = fmaf(xv.z, rstd, nmu) * wsh[cb + 2] + bsh[cb + 2];
            float v3 = fmaf(xv.w, rstd, nmu) * wsh[cb + 3] + bsh[cb + 3];
            uint2 pk;
            pk.x = pack_bf2(v0, v1);
            pk.y = pack_bf2(v2, v3);
            *reinterpret_cast<uint2*>(&Bs[u * BS_HS + cb]) = pk;
        }
        __syncthreads();
        #pragma unroll
        for (int s = 0; s < 4; s++) {
            int kk16 = s * 16;
            uint32_t a[2][4];
            #pragma unroll
            for (int mt = 0; mt < 2; mt++)
                ldsm4(a[mt][0], a[mt][1], a[mt][2], a[mt][3],
                      &As[(bm + mt * 16 + a_row) * AS_HS + kk16 + a_koff]);
            #pragma unroll
            for (int q = 0; q < 8; q++) {
                uint32_t t0r, t1r, t2r, t3r;
                ldsm4t(t0r, t1r, t2r, t3r,
                       &Bs[(kk16 + b_krow) * BS_HS + bn + q * 16 + b_noff]);
                mma16816(acc[0][2*q],   a[0], t0r, t1r);
                mma16816(acc[0][2*q+1], a[0], t2r, t3r);
                mma16816(acc[1][2*q],   a[1], t0r, t1r);
                mma16816(acc[1][2*q+1], a[1], t2r, t3r);
            }
        }
        __syncthreads();
    }

    // epilogue: x2 = x + acc*gain*gctx
    #pragma unroll
    for (int mt = 0; mt < 2; mt++) {
        #pragma unroll
        for (int nt = 0; nt < 16; nt++) {
            int t = t0 + bm + mt * 16 + r;
            int c = c0 + bn + nt * 8 + cq * 2;
            float s0 = gain[c]     * gctx_b[c];
            float s1 = gain[c + 1] * gctx_b[c + 1];
            size_t ro = ((size_t)b * Tt + t) * Cc + c;
            float2 xr0 = *reinterpret_cast<const float2*>(&x[ro]);
            float2 o0;
            o0.x = xr0.x + acc[mt][nt][0] * s0;
            o0.y = xr0.y + acc[mt][nt][1] * s1;
            *reinterpret_cast<float2*>(&out[ro]) = o0;
            float2 xr1 = *reinterpret_cast<const float2*>(&x[ro + 8 * Cc]);
            float2 o1;
            o1.x = xr1.x + acc[mt][nt][2] * s0;
            o1.y = xr1.y + acc[mt][nt][3] * s1;
            *reinterpret_cast<float2*>(&out[ro + 8 * Cc]) = o1;
        }
    }
}

#define CONV_SMEM (32768 + 128*AS_HS*2 + 64*BS_HS*2)   // 32768+18432+33792 = 84992

__global__ __launch_bounds__(256)
void conv_pass1_kernel(const float* __restrict__ x,
                       const float* __restrict__ lnw,
                       const float* __restrict__ lnb,
                       const float* __restrict__ gain,
                       float* out) {
    int b = blockIdx.z;
    if (b == 0 && blockIdx.y == 0) return;           // scratch tile -> fixup
    int t0 = blockIdx.y * 128;
    int c0 = blockIdx.x * CTN;
    extern __shared__ char sm[];
    float* sh_h = reinterpret_cast<float*>(sm);
    __nv_bfloat16* As = reinterpret_cast<__nv_bfloat16*>(sm + 32768);
    __nv_bfloat16* Bs = reinterpret_cast<__nv_bfloat16*>(sm + 32768 + 128*AS_HS*2);
    __shared__ float wsh[CTN], bsh[CTN];
    int tid = threadIdx.x;
    const float* hG = out + OFF_H;
    for (int i = tid * 4; i < NFFT; i += 1024)
        *reinterpret_cast<float4*>(&sh_h[i]) = *reinterpret_cast<const float4*>(&hG[i]);
    if (tid < CTN) { wsh[tid] = lnw[c0 + tid]; bsh[tid] = lnb[c0 + tid]; }
    __syncthreads();
    conv_tile_mma(x, out, b, t0, c0, sh_h,
                  out + OFF_MU + (size_t)b * Tt, out + OFF_RS + (size_t)b * Tt,
                  wsh, bsh, gain, out + OFF_GC + (size_t)b * Cc, As, Bs, tid);
}

#define FIXUP_SMEM (32768 + 16384 + 16384 + 128*AS_HS*2 + 64*BS_HS*2)  // 117760

__global__ __launch_bounds__(256)
void conv_fixup_kernel(const float* __restrict__ x,
                       const float* __restrict__ lnw,
                       const float* __restrict__ lnb,
                       const float* __restrict__ gain,
                       float* out) {
    extern __shared__ char sm[];
    float* sh_h = reinterpret_cast<float*>(sm);
    float* smu  = reinterpret_cast<float*>(sm + 32768);
    float* srs  = reinterpret_cast<float*>(sm + 49152);
    __nv_bfloat16* As = reinterpret_cast<__nv_bfloat16*>(sm + 65536);
    __nv_bfloat16* Bs = reinterpret_cast<__nv_bfloat16*>(sm + 65536 + 128*AS_HS*2);
    __shared__ float wsh[CTN], bsh[CTN], sgc[CTN];
    int tid = threadIdx.x;
    int c0 = blockIdx.x * CTN;

    for (int i = tid; i < NFFT; i += 256) sh_h[i] = out[OFF_H + i];
    for (int i = tid; i < Tt; i += 256) {
        smu[i] = out[OFF_MU + i];
        srs[i] = out[OFF_RS + i];
    }
    if (tid < CTN) {
        sgc[tid] = out[OFF_GC + c0 + tid];
        wsh[tid] = lnw[c0 + tid];
        bsh[tid] = lnb[c0 + tid];
    }
    __syncthreads();
    if (tid == 0) {       // all 4 co-resident blocks done copying scratch
        int* flag = reinterpret_cast<int*>(&out[OFF_FLAG]);
        atomicAdd(flag, 1);
        while (*reinterpret_cast<volatile int*>(flag) < 4) { }
    }
    __syncthreads();

    conv_tile_mma(x, out, 0, 0, c0, sh_h, smu, srs,
                  wsh, bsh, gain, sgc - c0, As, Bs, tid);
}

// ---------------------------------------------------------------------------
// Fused FFN via bf16 MMA + ldmatrix (R11 version — resident sf, staged ONCE
// before any in-place write; K-chunk 64, single-buffer).
// Block = 64 rows, 8 warps (2m x 4n). sf [64][1024] stride 1032;
// sht [64][256] stride 264; wst [64][256] stride 264.
// ---------------------------------------------------------------------------
#define MT 64
#define SF_HS  1032
#define SHT_HS 264
#define WST_HS 264
#define FFN_SMEM (MT*SF_HS*2 + MT*SHT_HS*2 + 64*WST_HS*2)   // 199680

__global__ __launch_bounds__(256)
void ffn_kernel(float* out,
                const float* __restrict__ flnw, const float* __restrict__ flnb,
                const float* __restrict__ w1, const float* __restrict__ b1,
                const float* __restrict__ w2, const float* __restrict__ b2) {
    extern __shared__ char sm[];
    __nv_bfloat16* sf  = reinterpret_cast<__nv_bfloat16*>(sm);
    __nv_bfloat16* sht = reinterpret_cast<__nv_bfloat16*>(sm + MT*SF_HS*2);
    __nv_bfloat16* wst = reinterpret_cast<__nv_bfloat16*>(sm + MT*SF_HS*2 + MT*SHT_HS*2);
    __shared__ float smu[MT], srs[MT];

    int tid = threadIdx.x;
    size_t r0 = (size_t)blockIdx.x * MT;
    int lane = tid & 31, wid = tid >> 5;
    int warp_m = wid & 1, warp_n = wid >> 1;
    int bm = warp_m * 32, bn = warp_n * 64;
    int r = lane >> 2, cq = lane & 3;
    const int a_row = (lane & 15), a_koff = (lane >> 4) * 8;
    const int b_krow = (lane & 7) + ((lane >> 3) & 1) * 8;
    const int b_noff = (lane >> 4) * 8;

    // LN2 stats (warp per row)
    for (int rr = wid; rr < MT; rr += 8) {
        const float* row = out + (r0 + rr) * Cc;
        float s = 0.f, q = 0.f;
        for (int i = lane; i < Cc; i += 32) { float v = row[i]; s += v; q = fmaf(v, v, q); }
        for (int o = 16; o > 0; o >>= 1) {
            s += __shfl_xor_sync(0xFFFFFFFFu, s, o);
            q += __shfl_xor_sync(0xFFFFFFFFu, q, o);
        }
        if (lane == 0) {
            float m = s * (1.f / Cc);
            smu[rr] = m;
            srs[rr] = rsqrtf(q * (1.f / Cc) - m * m + EPSv);
        }
    }
    __syncthreads();

    // stage sf = LN(x2) bf16 (ONCE, before any write to out)
    for (int i = tid * 4; i < MT * Cc; i += 1024) {
        int row = i >> 10, col = i & 1023;
        float4 v = *reinterpret_cast<const float4*>(&out[(r0 + row) * Cc + col]);
        float rs = srs[row];
        float nmu = -smu[row] * rs;
        float4 wv = *reinterpret_cast<const float4*>(&flnw[col]);
        float4 bv = *reinterpret_cast<const float4*>(&flnb[col]);
        uint2 pk;
        pk.x = pack_bf2(fmaf(v.x, rs, nmu) * wv.x + bv.x, fmaf(v.y, rs, nmu) * wv.y + bv.y);
        pk.y = pack_bf2(fmaf(v.z, rs, nmu) * wv.z + bv.z, fmaf(v.w, rs, nmu) * wv.w + bv.w);
        *reinterpret_cast<uint2*>(&sf[row * SF_HS + col]) = pk;
    }
    __syncthreads();

    for (int hc = 0; hc < Hh; hc += 256) {
        // ---- GEMM1: sht[64,256] = gelu(sf @ w1[:,hc:hc+256] + b1) ----
        float acc[2][8][4];
        #pragma unroll
        for (int mt = 0; mt < 2; mt++)
            #pragma unroll
            for (int nt = 0; nt < 8; nt++)
                #pragma unroll
                for (int j = 0; j < 4; j++) acc[mt][nt][j] = 0.f;

        for (int k0 = 0; k0 < Cc; k0 += 64) {
            #pragma unroll
            for (int l = 0; l < 16; l++) {     // stage w1 [k=64][n=256]
                int i = tid + l * 256;
                int k = i >> 6, cb = (i & 63) * 4;
                float4 wv = *reinterpret_cast<const float4*>(
                    &w1[(size_t)(k0 + k) * Hh + hc + cb]);
                uint2 pk;
                pk.x = pack_bf2(wv.x, wv.y);
                pk.y = pack_bf2(wv.z, wv.w);
                *reinterpret_cast<uint2*>(&wst[k * WST_HS + cb]) = pk;
            }
            __syncthreads();
            #pragma unroll
            for (int s = 0; s < 4; s++) {
                int kk16 = s * 16;
                uint32_t a[2][4];
                #pragma unroll
                for (int mt = 0; mt < 2; mt++)
                    ldsm4(a[mt][0], a[mt][1], a[mt][2], a[mt][3],
                          &sf[(bm + mt * 16 + a_row) * SF_HS + k0 + kk16 + a_koff]);
                #pragma unroll
                for (int q = 0; q < 4; q++) {
                    uint32_t t0r, t1r, t2r, t3r;
                    ldsm4t(t0r, t1r, t2r, t3r,
                           &wst[(kk16 + b_krow) * WST_HS + bn + q * 16 + b_noff]);
                    mma16816(acc[0][2*q],   a[0], t0r, t1r);
                    mma16816(acc[0][2*q+1], a[0], t2r, t3r);
                    mma16816(acc[1][2*q],   a[1], t0r, t1r);
                    mma16816(acc[1][2*q+1], a[1], t2r, t3r);
                }
            }
            __syncthreads();
        }
        // epilogue1: bias + gelu -> sht
        #pragma unroll
        for (int mt = 0; mt < 2; mt++) {
            #pragma unroll
            for (int nt = 0; nt < 8; nt++) {
                int row = bm + mt * 16 + r;
                int col = bn + nt * 8 + cq * 2;
                float bb0 = b1[hc + col], bb1 = b1[hc + col + 1];
                float v0 = acc[mt][nt][0] + bb0;
                float v1 = acc[mt][nt][1] + bb1;
                float v2 = acc[mt][nt][2] + bb0;
                float v3 = acc[mt][nt][3] + bb1;
                v0 = 0.5f * v0 * (1.f + erff(v0 * 0.70710678118654752f));
                v1 = 0.5f * v1 * (1.f + erff(v1 * 0.70710678118654752f));
                v2 = 0.5f * v2 * (1.f + erff(v2 * 0.70710678118654752f));
                v3 = 0.5f * v3 * (1.f + erff(v3 * 0.70710678118654752f));
                *reinterpret_cast<uint32_t*>(&sht[row * SHT_HS + col])       = pack_bf2(v0, v1);
                *reinterpret_cast<uint32_t*>(&sht[(row + 8) * SHT_HS + col]) = pack_bf2(v2, v3);
            }
        }
        __syncthreads();

        // ---- GEMM2: out[64,:] += sht @ w2[hc:hc+256,:] (+ b2 on hc==0) ----
        for (int cc0 = 0; cc0 < Cc; cc0 += 256) {
            float acc2[2][8][4];
            #pragma unroll
            for (int mt = 0; mt < 2; mt++)
                #pragma unroll
                for (int nt = 0; nt < 8; nt++)
                    #pragma unroll
                    for (int j = 0; j < 4; j++) acc2[mt][nt][j] = 0.f;

            for (int k0 = 0; k0 < 256; k0 += 64) {
                #pragma unroll
                for (int l = 0; l < 16; l++) {     // stage w2 [k=64][n=256]
                    int i = tid + l * 256;
                    int k = i >> 6, cb = (i & 63) * 4;
                    float4 wv = *reinterpret_cast<const float4*>(
                        &w2[(size_t)(hc + k0 + k) * Cc + cc0 + cb]);
                    uint2 pk;
                    pk.x = pack_bf2(wv.x, wv.y);
                    pk.y = pack_bf2(wv.z, wv.w);
                    *reinterpret_cast<uint2*>(&wst[k * WST_HS + cb]) = pk;
                }
                __syncthreads();
                #pragma unroll
                for (int s = 0; s < 4; s++) {
                    int kk16 = s * 16;
                    uint32_t a[2][4];
                    #pragma unroll
                    for (int mt = 0; mt < 2; mt++)
                        ldsm4(a[mt][0], a[mt][1], a[mt][2], a[mt][3],
                              &sht[(bm + mt * 16 + a_row) * SHT_HS + k0 + kk16 + a_koff]);
                    #pragma unroll
                    for (int q = 0; q < 4; q++) {
                        uint32_t t0r, t1r, t2r, t3r;
                        ldsm4t(t0r, t1r, t2r, t3r,
                               &wst[(kk16 + b_krow) * WST_HS + bn + q * 16 + b_noff]);
                        mma16816(acc2[0][2*q],   a[0], t0r, t1r);
                        mma16816(acc2[0][2*q+1], a[0], t2r, t3r);
                        mma16816(acc2[1][2*q],   a[1], t0r, t1r);
                        mma16816(acc2[1][2*q+1], a[1], t2r, t3r);
                    }
                }
                __syncthreads();
            }
            // thread-private RMW into out (deterministic ownership)
            #pragma unroll
            for (int mt = 0; mt < 2; mt++) {
                #pragma unroll
                for (int nt = 0; nt < 8; nt++) {
                    int row = bm + mt * 16 + r;
                    int col = cc0 + bn + nt * 8 + cq * 2;
                    size_t ro = (r0 + row) * Cc + col;
                    float2 o0 = *reinterpret_cast<const float2*>(&out[ro]);
                    float2 o1 = *reinterpret_cast<const float2*>(&out[ro + 8 * Cc]);
                    if (hc == 0) {
                        float bb0 = b2[col], bb1 = b2[col + 1];
                        o0.x += bb0; o0.y += bb1;
                        o1.x += bb0; o1.y += bb1;
                    }
                    o0.x += acc2[mt][nt][0]; o0.y += acc2[mt][nt][1];
                    o1.x += acc2[mt][nt][2]; o1.y += acc2[mt][nt][3];
                    *reinterpret_cast<float2*>(&out[ro]) = o0;
                    *reinterpret_cast<float2*>(&out[ro + 8 * Cc]) = o1;
                }
            }
        }
        __syncthreads();
    }
}

// ---------------------------------------------------------------------------
// kernel_launch
// ---------------------------------------------------------------------------
extern "C" void kernel_launch(void* const* d_in, const int* in_sizes, int n_in,
                              void* d_out, int out_size) {
    const float* x    = (const float*)d_in[0];
    const float* kern = (const float*)d_in[1];
    const float* gain = (const float*)d_in[2];
    const float* gfl  = (const float*)d_in[3];
    const float* gcw  = (const float*)d_in[4];
    const float* gcb  = (const float*)d_in[5];
    const float* lnw  = (const float*)d_in[6];
    const float* lnb  = (const float*)d_in[7];
    const float* flnw = (const float*)d_in[8];
    const float* flnb = (const float*)d_in[9];
    const float* w1   = (const float*)d_in[10];
    const float* b1   = (const float*)d_in[11];
    const float* w2   = (const float*)d_in[12];
    const float* b2   = (const float*)d_in[13];
    const int*   cut  = (const int*)d_in[14];
    float* out = (float*)d_out;

    cudaFuncSetAttribute(conv_pass1_kernel,
                         cudaFuncAttributeMaxDynamicSharedMemorySize, CONV_SMEM);
    cudaFuncSetAttribute(conv_fixup_kernel,
                         cudaFuncAttributeMaxDynamicSharedMemorySize, FIXUP_SMEM);
    cudaFuncSetAttribute(ffn_kernel,
                         cudaFuncAttributeMaxDynamicSharedMemorySize, FFN_SMEM);

    ln_stats_kernel<<<NROWS, 256>>>(x, out + OFF_MU, out + OFF_RS);
    sred_kernel<<<Bb, 256>>>(out + OFF_MU, out + OFF_RS, out + OFF_S);
    pooled_part_kernel<<<dim3(NSP, Bb), 256>>>(x, out + OFF_RS, out + OFF_PP);
    pooled_reduce_kernel<<<(Bb * Cc) / 256, 256>>>(out + OFF_PP, out + OFF_S,
                                                   lnw, lnb, out + OFF_PL);
    gctx_kernel<<<Bb * (Cc / 64), 256>>>(out + OFF_PL, gcw, gcb, out + OFF_GC);
    freq_kernel<<<(FB + 255) / 256, 256>>>(kern, gfl, cut, out + OFF_WRE, out + OFF_WIM);
    hfilt_kernel<<<NFFT / 256, 256>>>(out + OFF_WRE, out + OFF_WIM,
                                      out + OFF_H, out + OFF_FLAG);
    conv_pass1_kernel<<<dim3(Cc / CTN, Tt / 128, Bb), 256, CONV_SMEM>>>(
        x, lnw, lnb, gain, out);
    conv_fixup_kernel<<<Cc / CTN, 256, FIXUP_SMEM>>>(x, lnw, lnb, gain, out);
    ffn_kernel<<<NROWS / MT, 256, FFN_SMEM>>>(out, flnw, flnb, w1, b1, w2, b2);
}

// round 15
// speedup vs baseline: 1.0585x; 1.0080x over previous
#include <cuda_runtime.h>
#include <cuda_bf16.h>
#include <math.h>
#include <stdint.h>

// ---------------------------------------------------------------------------
// Problem constants (FixedSpectralBlock: B=4, T=4096, C=1024, K=1024)
// ---------------------------------------------------------------------------
#define Bb   4
#define Tt   4096
#define Cc   1024
#define Kk   1024
#define NFFT 8192
#define FB   4097          // NFFT/2 + 1
#define Hh   2048          // 2*C
#define EPSv 1e-5f
#define NROWS (Bb*Tt)
#define NSP  16            // pooled T-splits

// Scratch layout inside d_out rows 0..127 of batch 0 (conv pass-1 skips that
// tile; fixup reads scratch then overwrites it). Offsets in floats:
#define OFF_H    0        // hfilt          [8192]
#define OFF_WRE  8192     // W.re           [4160]
#define OFF_WIM  12352    // W.im           [4160]
#define OFF_MU   16512    // LN1 mean       [16384]
#define OFF_RS   32896    // LN1 rstd       [16384]
#define OFF_S    49280    // per-batch S    [8]
#define OFF_PL   49288    // pooled         [4096]
#define OFF_GC   53384    // gctx           [4096]
#define OFF_FLAG 58368    // fixup spin-barrier flag
#define OFF_PP   58376    // pooled partials [Bb*NSP*Cc = 65536] (end 123912)

// ---------------------------------------------------------------------------
// Helpers
// ---------------------------------------------------------------------------
__device__ __forceinline__ float2 block_reduce2(float a, float b) {
    __shared__ float sa[8], sb[8];
    for (int o = 16; o > 0; o >>= 1) {
        a += __shfl_xor_sync(0xFFFFFFFFu, a, o);
        b += __shfl_xor_sync(0xFFFFFFFFu, b, o);
    }
    int w = threadIdx.x >> 5, l = threadIdx.x & 31;
    if (l == 0) { sa[w] = a; sb[w] = b; }
    __syncthreads();
    if (w == 0) {
        a = (l < 8) ? sa[l] : 0.f;
        b = (l < 8) ? sb[l] : 0.f;
        for (int o = 4; o > 0; o >>= 1) {
            a += __shfl_xor_sync(0xFFFFFFFFu, a, o);
            b += __shfl_xor_sync(0xFFFFFFFFu, b, o);
        }
        if (l == 0) { sa[0] = a; sb[0] = b; }
    }
    __syncthreads();
    return make_float2(sa[0], sb[0]);
}

__device__ __forceinline__ uint32_t pack_bf2(float lo, float hi) {
    __nv_bfloat162 h = __floats2bfloat162_rn(lo, hi);
    return *reinterpret_cast<uint32_t*>(&h);
}

__device__ __forceinline__ uint32_t smem_cast(const void* p) {
    return (uint32_t)__cvta_generic_to_shared(p);
}

__device__ __forceinline__ void ldsm4(uint32_t& r0, uint32_t& r1,
                                      uint32_t& r2, uint32_t& r3,
                                      const void* p) {
    uint32_t a = smem_cast(p);
    asm volatile("ldmatrix.sync.aligned.m8n8.x4.shared.b16 {%0,%1,%2,%3},[%4];"
                 : "=r"(r0), "=r"(r1), "=r"(r2), "=r"(r3) : "r"(a));
}
__device__ __forceinline__ void ldsm4t(uint32_t& r0, uint32_t& r1,
                                       uint32_t& r2, uint32_t& r3,
                                       const void* p) {
    uint32_t a = smem_cast(p);
    asm volatile("ldmatrix.sync.aligned.m8n8.x4.trans.shared.b16 {%0,%1,%2,%3},[%4];"
                 : "=r"(r0), "=r"(r1), "=r"(r2), "=r"(r3) : "r"(a));
}

// m16n8k16 bf16 MMA, fp32 accumulate
__device__ __forceinline__ void mma16816(float* c, const uint32_t* a,
                                         uint32_t b0, uint32_t b1) {
    asm volatile(
        "mma.sync.aligned.m16n8k16.row.col.f32.bf16.bf16.f32 "
        "{%0,%1,%2,%3}, {%4,%5,%6,%7}, {%8,%9}, {%0,%1,%2,%3};\n"
        : "+f"(c[0]), "+f"(c[1]), "+f"(c[2]), "+f"(c[3])
        : "r"(a[0]), "r"(a[1]), "r"(a[2]), "r"(a[3]), "r"(b0), "r"(b1));
}

// ---------------------------------------------------------------------------
// Pre-kernels
// ---------------------------------------------------------------------------
__global__ __launch_bounds__(256)
void ln_stats_kernel(const float* __restrict__ x, float* mu, float* rs) {
    size_t row = blockIdx.x;
    float4 v = reinterpret_cast<const float4*>(x + row * Cc)[threadIdx.x];
    float s  = v.x + v.y + v.z + v.w;
    float sq = v.x*v.x + v.y*v.y + v.z*v.z + v.w*v.w;
    float2 r = block_reduce2(s, sq);
    if (threadIdx.x == 0) {
        float mean = r.x * (1.f / Cc);
        float var  = r.y * (1.f / Cc) - mean * mean;
        mu[row] = mean;
        rs[row] = rsqrtf(var + EPSv);
    }
}

__global__ __launch_bounds__(256)
void sred_kernel(const float* mu, const float* rs, float* S) {
    int b = blockIdx.x;
    float a = 0.f;
    for (int t = threadIdx.x; t < Tt; t += 256)
        a += mu[b * Tt + t] * rs[b * Tt + t];
    float2 r = block_reduce2(a, 0.f);
    if (threadIdx.x == 0) S[b] = r.x * (1.f / Tt);
}

__global__ __launch_bounds__(256)
void pooled_part_kernel(const float* __restrict__ x, const float* rs,
                        float* partial) {
    int b = blockIdx.y, sp = blockIdx.x;
    int t0 = sp * (Tt / NSP);
    __shared__ float srs[Tt / NSP];
    for (int i = threadIdx.x; i < Tt / NSP; i += 256) srs[i] = rs[b * Tt + t0 + i];
    __syncthreads();
    int c = threadIdx.x * 4;
    float4 acc = make_float4(0.f, 0.f, 0.f, 0.f);
    for (int r = 0; r < Tt / NSP; r++) {
        float4 v = *reinterpret_cast<const float4*>(
            &x[((size_t)b * Tt + t0 + r) * Cc + c]);
        float w = srs[r];
        acc.x = fmaf(v.x, w, acc.x);
        acc.y = fmaf(v.y, w, acc.y);
        acc.z = fmaf(v.z, w, acc.z);
        acc.w = fmaf(v.w, w, acc.w);
    }
    *reinterpret_cast<float4*>(&partial[((size_t)b * NSP + sp) * Cc + c]) = acc;
}

__global__ __launch_bounds__(256)
void pooled_reduce_kernel(const float* partial, const float* S,
                          const float* __restrict__ lnw,
                          const float* __restrict__ lnb,
                          float* pooled) {
    int idx = blockIdx.x * 256 + threadIdx.x;
    int b = idx / Cc, c = idx % Cc;
    float a = 0.f;
    #pragma unroll
    for (int sp = 0; sp < NSP; sp++)
        a += partial[((size_t)b * NSP + sp) * Cc + c];
    pooled[idx] = lnw[c] * (a * (1.f / Tt) - S[b]) + lnb[c];
}

__global__ __launch_bounds__(256)
void gctx_kernel(const float* pooled,
                 const float* __restrict__ W,
                 const float* __restrict__ bias,
                 float* gctx) {
    int b  = blockIdx.x >> 4;
    int cb = blockIdx.x & 15;
    __shared__ float pb[Cc];
    __shared__ float red[256];
    for (int i = threadIdx.x; i < Cc; i += 256) pb[i] = pooled[b * Cc + i];
    __syncthreads();
    int o = threadIdx.x >> 2, ks = threadIdx.x & 3;
    int c = cb * 64 + o;
    float a = 0.f;
    int k0 = ks * 256;
    #pragma unroll 4
    for (int k = k0; k < k0 + 256; k++)
        a = fmaf(pb[k], W[(size_t)k * Cc + c], a);
    red[threadIdx.x] = a;
    __syncthreads();
    if (ks == 0) {
        float t = red[o*4] + red[o*4+1] + red[o*4+2] + red[o*4+3] + bias[c];
        gctx[b * Cc + c] = 1.f / (1.f + expf(-t));
    }
}

__device__ __forceinline__ float freq_mask_val(int f, int cut) {
    float mask = 1.f;
    if (cut < FB) {
        int tr = cut < 16 ? cut : 16;
        if (f >= cut) mask = 0.f;
        else if (tr > 0 && f >= cut - tr) {
            int i = f - (cut - tr);
            float tt = (tr > 1) ? (float)i / (float)(tr - 1) : 0.f;
            mask = 0.5f * (1.f + cospif(tt));
        }
    }
    return mask;
}

__global__ __launch_bounds__(256)
void freq_kernel(const float* __restrict__ kern,
                 const float* __restrict__ logits,
                 const int* __restrict__ cutp,
                 float* Wre, float* Wim) {
    __shared__ float ks[Kk];
    for (int i = threadIdx.x; i < Kk; i += 256) ks[i] = kern[i];
    __syncthreads();
    int f = blockIdx.x * 256 + threadIdx.x;
    if (f >= FB) return;
    float dc, ds;
    sincospif((float)f * (1.f / (NFFT / 2)), &ds, &dc);
    float re = 0.f, im = 0.f;
    for (int k0 = 0; k0 < Kk; k0 += 64) {
        int p = (f * k0) & (NFFT - 1);
        float c, sv;
        sincospif((float)p * (1.f / (NFFT / 2)), &sv, &c);
        #pragma unroll
        for (int k = k0; k < k0 + 64; k++) {
            float kv = ks[k];
            re = fmaf(kv,  c, re);
            im = fmaf(kv, -sv, im);
            float c2 = c * dc - sv * ds;
            sv = sv * dc + c * ds;
            c = c2;
        }
    }
    float g = 1.f / (1.f + expf(-logits[f]));
    float mask = freq_mask_val(f, *cutp);
    float coef = ((f == 0) || (f == NFFT / 2)) ? (1.f / NFFT) : (2.f / NFFT);
    float wgt = g * mask * coef;
    Wre[f] = re * wgt;
    Wim[f] = im * wgt;
}

__global__ __launch_bounds__(256)
void hfilt_kernel(const float* Wre, const float* Wim, float* h, float* flagp) {
    if (blockIdx.x == 0 && threadIdx.x == 0)
        *reinterpret_cast<int*>(flagp) = 0;
    __shared__ float sr[512], si[512];
    int s = blockIdx.x * 256 + threadIdx.x;
    float dc, dsn;
    sincospif((float)s * (1.f / (NFFT / 2)), &dsn, &dc);
    float acc = 0.f;
    for (int f0 = 0; f0 < FB; f0 += 512) {
        int n = min(512, FB - f0);
        __syncthreads();
        for (int i = threadIdx.x; i < n; i += 256) { sr[i] = Wre[f0 + i]; si[i] = Wim[f0 + i]; }
        __syncthreads();
        for (int ii = 0; ii < n; ii += 64) {
            int p = ((f0 + ii) * s) & (NFFT - 1);
            float c, sv;
            sincospif((float)p * (1.f / (NFFT / 2)), &sv, &c);
            int lim = min(ii + 64, n);
            #pragma unroll 4
            for (int i = ii; i < lim; i++) {
                acc = fmaf(sr[i],  c, acc);
                acc = fmaf(-si[i], sv, acc);
                float c2 = c * dc - sv * dsn;
                sv = sv * dc + c * dsn;
                c = c2;
            }
        }
    }
    h[s] = acc;
}

// ---------------------------------------------------------------------------
// Conv tile via bf16 MMA + ldmatrix (R11 single-buffer version, 128x128).
// As [128][64] stride 72; Bs [64][128] stride 136.
// ---------------------------------------------------------------------------
#define AS_HS 72
#define BS_HS 136

__device__ void conv_tile_mma(const float* __restrict__ x, float* out,
                              int b, int t0, int c0,
                              const float* sh_h,
                              const float* muArr, const float* rsArr,
                              const float* wsh, const float* bsh,
                              const float* __restrict__ gain,
                              const float* gctx_b,
                              __nv_bfloat16* As, __nv_bfloat16* Bs,
                              int tid) {
    const int lane = tid & 31, wid = tid >> 5;
    const int warp_m = wid & 3, warp_n = wid >> 2;
    const int bm = warp_m * 32, bn = warp_n * 64;
    const int r = lane >> 2, cq = lane & 3;
    const float* xb = x + (size_t)b * Tt * Cc;
    const int a_row = (lane & 15), a_koff = (lane >> 4) * 8;
    const int b_krow = (lane & 7) + ((lane >> 3) & 1) * 8;
    const int b_noff = (lane >> 4) * 8;

    float acc[2][8][4];
    #pragma unroll
    for (int mt = 0; mt < 2; mt++)
        #pragma unroll
        for (int nt = 0; nt < 8; nt++)
            #pragma unroll
            for (int j = 0; j < 4; j++) acc[mt][nt][j] = 0.f;

    for (int k0 = 0; k0 < Tt; k0 += 64) {
        #pragma unroll
        for (int l = 0; l < 4; l++) {
            int i = tid + l * 256;
            int m = i >> 3, k8 = (i & 7) * 8;
            int base = t0 + m - k0 - k8;
            uint4 v;
            v.x = pack_bf2(sh_h[(base    ) & (NFFT-1)], sh_h[(base - 1) & (NFFT-1)]);
            v.y = pack_bf2(sh_h[(base - 2) & (NFFT-1)], sh_h[(base - 3) & (NFFT-1)]);
            v.z = pack_bf2(sh_h[(base - 4) & (NFFT-1)], sh_h[(base - 5) & (NFFT-1)]);
            v.w = pack_bf2(sh_h[(base - 6) & (NFFT-1)], sh_h[(base - 7) & (NFFT-1)]);
            *reinterpret_cast<uint4*>(&As[m * AS_HS + k8]) = v;
        }
        #pragma unroll
        for (int l = 0; l < 8; l++) {
            int i = tid + l * 256;
            int u = i >> 5, cb = (i & 31) * 4;
            int ug = k0 + u;
            float rstd = rsArr[ug];
            float nmu  = -muArr[ug] * rstd;
            float4 xv = *reinterpret_cast<const float4*>(&xb[(size_t)ug * Cc + c0 + cb]);
            float v0 = fmaf(xv.x, rstd, nmu) * wsh[cb]     + bsh[cb];
            float v1 = fmaf(xv.y, rstd, nmu) * wsh[cb + 1] + bsh[cb + 1];
            float v2 = fmaf(xv.z, rstd, nmu) * wsh[cb + 2] + bsh[cb + 2];
            float v3 = fmaf(xv.w, rstd, nmu) * wsh[cb + 3] + bsh[cb + 3];
            uint2 pk;
            pk.x = pack_bf2(v0, v1);
            pk.y = pack_bf2(v2, v3);
            *reinterpret_cast<uint2*>(&Bs[u * BS_HS + cb]) = pk;
        }
        __syncthreads();
        #pragma unroll
        for (int s = 0; s < 4; s++) {
            int kk16 = s * 16;
            uint32_t a[2][4];
            #pragma unroll
            for (int mt = 0; mt < 2; mt++)
                ldsm4(a[mt][0], a[mt][1], a[mt][2], a[mt][3],
                      &As[(bm + mt * 16 + a_row) * AS_HS + kk16 + a_koff]);
            #pragma unroll
            for (int q = 0; q < 4; q++) {
                uint32_t t0r, t1r, t2r, t3r;
                ldsm4t(t0r, t1r, t2r, t3r,
                       &Bs[(kk16 + b_krow) * BS_HS + bn + q * 16 + b_noff]);
                mma16816(acc[0][2*q],   a[0], t0r, t1r);
                mma16816(acc[0][2*q+1], a[0], t2r, t3r);
                mma16816(acc[1][2*q],   a[1], t0r, t1r);
                mma16816(acc[1][2*q+1], a[1], t2r, t3r);
            }
        }
        __syncthreads();
    }

    #pragma unroll
    for (int mt = 0; mt < 2; mt++) {
        #pragma unroll
        for (int nt = 0; nt < 8; nt++) {
            int t = t0 + bm + mt * 16 + r;
            int c = c0 + bn + nt * 8 + cq * 2;
            float s0 = gain[c]     * gctx_b[c];
            float s1 = gain[c + 1] * gctx_b[c + 1];
            size_t ro = ((size_t)b * Tt + t) * Cc + c;
            float2 xr0 = *reinterpret_cast<const float2*>(&x[ro]);
            float2 o0;
            o0.x = xr0.x + acc[mt][nt][0] * s0;
            o0.y = xr0.y + acc[mt][nt][1] * s1;
            *reinterpret_cast<float2*>(&out[ro]) = o0;
            float2 xr1 = *reinterpret_cast<const float2*>(&x[ro + 8 * Cc]);
            float2 o1;
            o1.x = xr1.x + acc[mt][nt][2] * s0;
            o1.y = xr1.y + acc[mt][nt][3] * s1;
            *reinterpret_cast<float2*>(&out[ro + 8 * Cc]) = o1;
        }
    }
}

#define CONV_SMEM (32768 + 128*AS_HS*2 + 64*BS_HS*2)   // 68608

__global__ __launch_bounds__(256)
void conv_pass1_kernel(const float* __restrict__ x,
                       const float* __restrict__ lnw,
                       const float* __restrict__ lnb,
                       const float* __restrict__ gain,
                       float* out) {
    int b = blockIdx.z;
    if (b == 0 && blockIdx.y == 0) return;           // scratch tile -> fixup
    int t0 = blockIdx.y * 128;
    int c0 = blockIdx.x * 128;
    extern __shared__ char sm[];
    float* sh_h = reinterpret_cast<float*>(sm);
    __nv_bfloat16* As = reinterpret_cast<__nv_bfloat16*>(sm + 32768);
    __nv_bfloat16* Bs = reinterpret_cast<__nv_bfloat16*>(sm + 32768 + 128*AS_HS*2);
    __shared__ float wsh[128], bsh[128];
    int tid = threadIdx.x;
    const float* hG = out + OFF_H;
    for (int i = tid * 4; i < NFFT; i += 1024)
        *reinterpret_cast<float4*>(&sh_h[i]) = *reinterpret_cast<const float4*>(&hG[i]);
    if (tid < 128) { wsh[tid] = lnw[c0 + tid]; bsh[tid] = lnb[c0 + tid]; }
    __syncthreads();
    conv_tile_mma(x, out, b, t0, c0, sh_h,
                  out + OFF_MU + (size_t)b * Tt, out + OFF_RS + (size_t)b * Tt,
                  wsh, bsh, gain, out + OFF_GC + (size_t)b * Cc, As, Bs, tid);
}

#define FIXUP_SMEM (32768 + 16384 + 16384 + 128*AS_HS*2 + 64*BS_HS*2)  // 101376

__global__ __launch_bounds__(256)
void conv_fixup_kernel(const float* __restrict__ x,
                       const float* __restrict__ lnw,
                       const float* __restrict__ lnb,
                       const float* __restrict__ gain,
                       float* out) {
    extern __shared__ char sm[];
    float* sh_h = reinterpret_cast<float*>(sm);
    float* smu  = reinterpret_cast<float*>(sm + 32768);
    float* srs  = reinterpret_cast<float*>(sm + 49152);
    __nv_bfloat16* As = reinterpret_cast<__nv_bfloat16*>(sm + 65536);
    __nv_bfloat16* Bs = reinterpret_cast<__nv_bfloat16*>(sm + 65536 + 128*AS_HS*2);
    __shared__ float wsh[128], bsh[128], sgc[128];
    int tid = threadIdx.x;
    int c0 = blockIdx.x * 128;

    for (int i = tid; i < NFFT; i += 256) sh_h[i] = out[OFF_H + i];
    for (int i = tid; i < Tt; i += 256) {
        smu[i] = out[OFF_MU + i];
        srs[i] = out[OFF_RS + i];
    }
    if (tid < 128) {
        sgc[tid] = out[OFF_GC + c0 + tid];
        wsh[tid] = lnw[c0 + tid];
        bsh[tid] = lnb[c0 + tid];
    }
    __syncthreads();
    if (tid == 0) {       // all 8 co-resident blocks done copying scratch
        int* flag = reinterpret_cast<int*>(&out[OFF_FLAG]);
        atomicAdd(flag, 1);
        while (*reinterpret_cast<volatile int*>(flag) < 8) { }
    }
    __syncthreads();

    conv_tile_mma(x, out, 0, 0, c0, sh_h, smu, srs,
                  wsh, bsh, gain, sgc - c0, As, Bs, tid);
}

// ---------------------------------------------------------------------------
// Fused FFN via bf16 MMA + ldmatrix — 512 THREADS (16 warps) for latency
// hiding; MT=64 rows, resident sf (staged once before any in-place write).
// Warp grid 4m x 4n; warp tile 16 x 64; acc 32 fp32/thread.
// sf [64][1024] stride 1032; sht [64][256] stride 264; wst [64][256] str 264.
// ---------------------------------------------------------------------------
#define MT 64
#define SF_HS  1032
#define SHT_HS 264
#define WST_HS 264
#define FFN_SMEM (MT*SF_HS*2 + MT*SHT_HS*2 + 64*WST_HS*2)   // 199680

__global__ __launch_bounds__(512)
void ffn_kernel(float* out,
                const float* __restrict__ flnw, const float* __restrict__ flnb,
                const float* __restrict__ w1, const float* __restrict__ b1,
                const float* __restrict__ w2, const float* __restrict__ b2) {
    extern __shared__ char sm[];
    __nv_bfloat16* sf  = reinterpret_cast<__nv_bfloat16*>(sm);
    __nv_bfloat16* sht = reinterpret_cast<__nv_bfloat16*>(sm + MT*SF_HS*2);
    __nv_bfloat16* wst = reinterpret_cast<__nv_bfloat16*>(sm + MT*SF_HS*2 + MT*SHT_HS*2);
    __shared__ float smu[MT], srs[MT];

    int tid = threadIdx.x;
    size_t r0 = (size_t)blockIdx.x * MT;
    int lane = tid & 31, wid = tid >> 5;            // wid 0..15
    int bm = (wid & 3) * 16;                        // 4 m-warps, 16 rows each
    int bn = (wid >> 2) * 64;                       // 4 n-warps, 64 cols each
    int r = lane >> 2, cq = lane & 3;
    const int a_row = (lane & 15), a_koff = (lane >> 4) * 8;
    const int b_krow = (lane & 7) + ((lane >> 3) & 1) * 8;
    const int b_noff = (lane >> 4) * 8;

    // LN2 stats (warp per row, 16 warps -> 4 rows each)
    for (int rr = wid; rr < MT; rr += 16) {
        const float* row = out + (r0 + rr) * Cc;
        float s = 0.f, q = 0.f;
        for (int i = lane; i < Cc; i += 32) { float v = row[i]; s += v; q = fmaf(v, v, q); }
        for (int o = 16; o > 0; o >>= 1) {
            s += __shfl_xor_sync(0xFFFFFFFFu, s, o);
            q += __shfl_xor_sync(0xFFFFFFFFu, q, o);
        }
        if (lane == 0) {
            float m = s * (1.f / Cc);
            smu[rr] = m;
            srs[rr] = rsqrtf(q * (1.f / Cc) - m * m + EPSv);
        }
    }
    __syncthreads();

    // stage sf = LN(x2) bf16 (ONCE, before any write to out)
    for (int i = tid * 4; i < MT * Cc; i += 2048) {
        int row = i >> 10, col = i & 1023;
        float4 v = *reinterpret_cast<const float4*>(&out[(r0 + row) * Cc + col]);
        float rs = srs[row];
        float nmu = -smu[row] * rs;
        float4 wv = *reinterpret_cast<const float4*>(&flnw[col]);
        float4 bv = *reinterpret_cast<const float4*>(&flnb[col]);
        uint2 pk;
        pk.x = pack_bf2(fmaf(v.x, rs, nmu) * wv.x + bv.x, fmaf(v.y, rs, nmu) * wv.y + bv.y);
        pk.y = pack_bf2(fmaf(v.z, rs, nmu) * wv.z + bv.z, fmaf(v.w, rs, nmu) * wv.w + bv.w);
        *reinterpret_cast<uint2*>(&sf[row * SF_HS + col]) = pk;
    }
    __syncthreads();

    for (int hc = 0; hc < Hh; hc += 256) {
        // ---- GEMM1: sht[64,256] = gelu(sf @ w1[:,hc:hc+256] + b1) ----
        float acc[8][4];
        #pragma unroll
        for (int nt = 0; nt < 8; nt++)
            #pragma unroll
            for (int j = 0; j < 4; j++) acc[nt][j] = 0.f;

        for (int k0 = 0; k0 < Cc; k0 += 64) {
            #pragma unroll
            for (int l = 0; l < 8; l++) {     // stage w1 [k=64][n=256]
                int i = tid + l * 512;
                int k = i >> 6, cb = (i & 63) * 4;
                float4 wv = *reinterpret_cast<const float4*>(
                    &w1[(size_t)(k0 + k) * Hh + hc + cb]);
                uint2 pk;
                pk.x = pack_bf2(wv.x, wv.y);
                pk.y = pack_bf2(wv.z, wv.w);
                *reinterpret_cast<uint2*>(&wst[k * WST_HS + cb]) = pk;
            }
            __syncthreads();
            #pragma unroll
            for (int s = 0; s < 4; s++) {
                int kk16 = s * 16;
                uint32_t a[4];
                ldsm4(a[0], a[1], a[2], a[3],
                      &sf[(bm + a_row) * SF_HS + k0 + kk16 + a_koff]);
                #pragma unroll
                for (int q = 0; q < 4; q++) {
                    uint32_t t0r, t1r, t2r, t3r;
                    ldsm4t(t0r, t1r, t2r, t3r,
                           &wst[(kk16 + b_krow) * WST_HS + bn + q * 16 + b_noff]);
                    mma16816(acc[2*q],   a, t0r, t1r);
                    mma16816(acc[2*q+1], a, t2r, t3r);
                }
            }
            __syncthreads();
        }
        // epilogue1: bias + gelu -> sht
        #pragma unroll
        for (int nt = 0; nt < 8; nt++) {
            int row = bm + r;
            int col = bn + nt * 8 + cq * 2;
            float bb0 = b1[hc + col], bb1 = b1[hc + col + 1];
            float v0 = acc[nt][0] + bb0;
            float v1 = acc[nt][1] + bb1;
            float v2 = acc[nt][2] + bb0;
            float v3 = acc[nt][3] + bb1;
            v0 = 0.5f * v0 * (1.f + erff(v0 * 0.70710678118654752f));
            v1 = 0.5f * v1 * (1.f + erff(v1 * 0.70710678118654752f));
            v2 = 0.5f * v2 * (1.f + erff(v2 * 0.70710678118654752f));
            v3 = 0.5f * v3 * (1.f + erff(v3 * 0.70710678118654752f));
            *reinterpret_cast<uint32_t*>(&sht[row * SHT_HS + col])       = pack_bf2(v0, v1);
            *reinterpret_cast<uint32_t*>(&sht[(row + 8) * SHT_HS + col]) = pack_bf2(v2, v3);
        }
        __syncthreads();

        // ---- GEMM2: out[64,:] += sht @ w2[hc:hc+256,:] (+ b2 on hc==0) ----
        for (int cc0 = 0; cc0 < Cc; cc0 += 256) {
            float acc2[8][4];
            #pragma unroll
            for (int nt = 0; nt < 8; nt++)
                #pragma unroll
                for (int j = 0; j < 4; j++) acc2[nt][j] = 0.f;

            for (int k0 = 0; k0 < 256; k0 += 64) {
                #pragma unroll
                for (int l = 0; l < 8; l++) {     // stage w2 [k=64][n=256]
                    int i = tid + l * 512;
                    int k = i >> 6, cb = (i & 63) * 4;
                    float4 wv = *reinterpret_cast<const float4*>(
                        &w2[(size_t)(hc + k0 + k) * Cc + cc0 + cb]);
                    uint2 pk;
                    pk.x = pack_bf2(wv.x, wv.y);
                    pk.y = pack_bf2(wv.z, wv.w);
                    *reinterpret_cast<uint2*>(&wst[k * WST_HS + cb]) = pk;
                }
                __syncthreads();
                #pragma unroll
                for (int s = 0; s < 4; s++) {
                    int kk16 = s * 16;
                    uint32_t a[4];
                    ldsm4(a[0], a[1], a[2], a[3],
                          &sht[(bm + a_row) * SHT_HS + k0 + kk16 + a_koff]);
                    #pragma unroll
                    for (int q = 0; q < 4; q++) {
                        uint32_t t0r, t1r, t2r, t3r;
                        ldsm4t(t0r, t1r, t2r, t3r,
                               &wst[(kk16 + b_krow) * WST_HS + bn + q * 16 + b_noff]);
                        mma16816(acc2[2*q],   a, t0r, t1r);
                        mma16816(acc2[2*q+1], a, t2r, t3r);
                    }
                }
                __syncthreads();
            }
            // thread-private RMW into out (static ownership: wid/lane only)
            #pragma unroll
            for (int nt = 0; nt < 8; nt++) {
                int row = bm + r;
                int col = cc0 + bn + nt * 8 + cq * 2;
                size_t ro = (r0 + row) * Cc + col;
                float2 o0 = *reinterpret_cast<const float2*>(&out[ro]);
                float2 o1 = *reinterpret_cast<const float2*>(&out[ro + 8 * Cc]);
                if (hc == 0) {
                    float bb0 = b2[col], bb1 = b2[col + 1];
                    o0.x += bb0; o0.y += bb1;
                    o1.x += bb0; o1.y += bb1;
                }
                o0.x += acc2[nt][0]; o0.y += acc2[nt][1];
                o1.x += acc2[nt][2]; o1.y += acc2[nt][3];
                *reinterpret_cast<float2*>(&out[ro]) = o0;
                *reinterpret_cast<float2*>(&out[ro + 8 * Cc]) = o1;
            }
        }
        __syncthreads();
    }
}

// ---------------------------------------------------------------------------
// kernel_launch
// ---------------------------------------------------------------------------
extern "C" void kernel_launch(void* const* d_in, const int* in_sizes, int n_in,
                              void* d_out, int out_size) {
    const float* x    = (const float*)d_in[0];
    const float* kern = (const float*)d_in[1];
    const float* gain = (const float*)d_in[2];
    const float* gfl  = (const float*)d_in[3];
    const float* gcw  = (const float*)d_in[4];
    const float* gcb  = (const float*)d_in[5];
    const float* lnw  = (const float*)d_in[6];
    const float* lnb  = (const float*)d_in[7];
    const float* flnw = (const float*)d_in[8];
    const float* flnb = (const float*)d_in[9];
    const float* w1   = (const float*)d_in[10];
    const float* b1   = (const float*)d_in[11];
    const float* w2   = (const float*)d_in[12];
    const float* b2   = (const float*)d_in[13];
    const int*   cut  = (const int*)d_in[14];
    float* out = (float*)d_out;

    cudaFuncSetAttribute(conv_pass1_kernel,
                         cudaFuncAttributeMaxDynamicSharedMemorySize, CONV_SMEM);
    cudaFuncSetAttribute(conv_fixup_kernel,
                         cudaFuncAttributeMaxDynamicSharedMemorySize, FIXUP_SMEM);
    cudaFuncSetAttribute(ffn_kernel,
                         cudaFuncAttributeMaxDynamicSharedMemorySize, FFN_SMEM);

    ln_stats_kernel<<<NROWS, 256>>>(x, out + OFF_MU, out + OFF_RS);
    sred_kernel<<<Bb, 256>>>(out + OFF_MU, out + OFF_RS, out + OFF_S);
    pooled_part_kernel<<<dim3(NSP, Bb), 256>>>(x, out + OFF_RS, out + OFF_PP);
    pooled_reduce_kernel<<<(Bb * Cc) / 256, 256>>>(out + OFF_PP, out + OFF_S,
                                                   lnw, lnb, out + OFF_PL);
    gctx_kernel<<<Bb * (Cc / 64), 256>>>(out + OFF_PL, gcw, gcb, out + OFF_GC);
    freq_kernel<<<(FB + 255) / 256, 256>>>(kern, gfl, cut, out + OFF_WRE, out + OFF_WIM);
    hfilt_kernel<<<NFFT / 256, 256>>>(out + OFF_WRE, out + OFF_WIM,
                                      out + OFF_H, out + OFF_FLAG);
    conv_pass1_kernel<<<dim3(Cc / 128, Tt / 128, Bb), 256, CONV_SMEM>>>(
        x, lnw, lnb, gain, out);
    conv_fixup_kernel<<<8, 256, FIXUP_SMEM>>>(x, lnw, lnb, gain, out);
    ffn_kernel<<<NROWS / MT, 512, FFN_SMEM>>>(out, flnw, flnb, w1, b1, w2, b2);
}

// round 16
// speedup vs baseline: 1.1224x; 1.0604x over previous
#include <cuda_runtime.h>
#include <cuda_bf16.h>
#include <math.h>
#include <stdint.h>

// ---------------------------------------------------------------------------
// Problem constants (FixedSpectralBlock: B=4, T=4096, C=1024, K=1024)
// ---------------------------------------------------------------------------
#define Bb   4
#define Tt   4096
#define Cc   1024
#define Kk   1024
#define NFFT 8192
#define FB   4097          // NFFT/2 + 1
#define Hh   2048          // 2*C
#define EPSv 1e-5f
#define NROWS (Bb*Tt)
#define NSP  16            // pooled T-splits

// Scratch layout inside d_out rows 0..127 of batch 0 (conv pass-1 skips that
// tile; fixup reads scratch then overwrites it). Offsets in floats:
#define OFF_H    0        // hfilt          [8192]
#define OFF_WRE  8192     // W.re           [4160]
#define OFF_WIM  12352    // W.im           [4160]
#define OFF_MU   16512    // LN1 mean       [16384]
#define OFF_RS   32896    // LN1 rstd       [16384]
#define OFF_S    49280    // per-batch S    [8]
#define OFF_PL   49288    // pooled         [4096]
#define OFF_GC   53384    // gctx           [4096]
#define OFF_FLAG 58368    // fixup spin-barrier flag
#define OFF_PP   58376    // pooled partials [Bb*NSP*Cc = 65536] (end 123912)

// ---------------------------------------------------------------------------
// Helpers
// ---------------------------------------------------------------------------
__device__ __forceinline__ float2 block_reduce2(float a, float b) {
    __shared__ float sa[8], sb[8];
    for (int o = 16; o > 0; o >>= 1) {
        a += __shfl_xor_sync(0xFFFFFFFFu, a, o);
        b += __shfl_xor_sync(0xFFFFFFFFu, b, o);
    }
    int w = threadIdx.x >> 5, l = threadIdx.x & 31;
    if (l == 0) { sa[w] = a; sb[w] = b; }
    __syncthreads();
    if (w == 0) {
        a = (l < 8) ? sa[l] : 0.f;
        b = (l < 8) ? sb[l] : 0.f;
        for (int o = 4; o > 0; o >>= 1) {
            a += __shfl_xor_sync(0xFFFFFFFFu, a, o);
            b += __shfl_xor_sync(0xFFFFFFFFu, b, o);
        }
        if (l == 0) { sa[0] = a; sb[0] = b; }
    }
    __syncthreads();
    return make_float2(sa[0], sb[0]);
}

__device__ __forceinline__ uint32_t pack_bf2(float lo, float hi) {
    __nv_bfloat162 h = __floats2bfloat162_rn(lo, hi);
    return *reinterpret_cast<uint32_t*>(&h);
}

__device__ __forceinline__ uint32_t smem_cast(const void* p) {
    return (uint32_t)__cvta_generic_to_shared(p);
}

__device__ __forceinline__ void ldsm4(uint32_t& r0, uint32_t& r1,
                                      uint32_t& r2, uint32_t& r3,
                                      const void* p) {
    uint32_t a = smem_cast(p);
    asm volatile("ldmatrix.sync.aligned.m8n8.x4.shared.b16 {%0,%1,%2,%3},[%4];"
                 : "=r"(r0), "=r"(r1), "=r"(r2), "=r"(r3) : "r"(a));
}
__device__ __forceinline__ void ldsm4t(uint32_t& r0, uint32_t& r1,
                                       uint32_t& r2, uint32_t& r3,
                                       const void* p) {
    uint32_t a = smem_cast(p);
    asm volatile("ldmatrix.sync.aligned.m8n8.x4.trans.shared.b16 {%0,%1,%2,%3},[%4];"
                 : "=r"(r0), "=r"(r1), "=r"(r2), "=r"(r3) : "r"(a));
}

// m16n8k16 bf16 MMA, fp32 accumulate
__device__ __forceinline__ void mma16816(float* c, const uint32_t* a,
                                         uint32_t b0, uint32_t b1) {
    asm volatile(
        "mma.sync.aligned.m16n8k16.row.col.f32.bf16.bf16.f32 "
        "{%0,%1,%2,%3}, {%4,%5,%6,%7}, {%8,%9}, {%0,%1,%2,%3};\n"
        : "+f"(c[0]), "+f"(c[1]), "+f"(c[2]), "+f"(c[3])
        : "r"(a[0]), "r"(a[1]), "r"(a[2]), "r"(a[3]), "r"(b0), "r"(b1));
}

// ---------------------------------------------------------------------------
// Pre-kernels
// ---------------------------------------------------------------------------
__global__ __launch_bounds__(256)
void ln_stats_kernel(const float* __restrict__ x, float* mu, float* rs) {
    size_t row = blockIdx.x;
    float4 v = reinterpret_cast<const float4*>(x + row * Cc)[threadIdx.x];
    float s  = v.x + v.y + v.z + v.w;
    float sq = v.x*v.x + v.y*v.y + v.z*v.z + v.w*v.w;
    float2 r = block_reduce2(s, sq);
    if (threadIdx.x == 0) {
        float mean = r.x * (1.f / Cc);
        float var  = r.y * (1.f / Cc) - mean * mean;
        mu[row] = mean;
        rs[row] = rsqrtf(var + EPSv);
    }
}

__global__ __launch_bounds__(256)
void sred_kernel(const float* mu, const float* rs, float* S) {
    int b = blockIdx.x;
    float a = 0.f;
    for (int t = threadIdx.x; t < Tt; t += 256)
        a += mu[b * Tt + t] * rs[b * Tt + t];
    float2 r = block_reduce2(a, 0.f);
    if (threadIdx.x == 0) S[b] = r.x * (1.f / Tt);
}

__global__ __launch_bounds__(256)
void pooled_part_kernel(const float* __restrict__ x, const float* rs,
                        float* partial) {
    int b = blockIdx.y, sp = blockIdx.x;
    int t0 = sp * (Tt / NSP);
    __shared__ float srs[Tt / NSP];
    for (int i = threadIdx.x; i < Tt / NSP; i += 256) srs[i] = rs[b * Tt + t0 + i];
    __syncthreads();
    int c = threadIdx.x * 4;
    float4 acc = make_float4(0.f, 0.f, 0.f, 0.f);
    for (int r = 0; r < Tt / NSP; r++) {
        float4 v = *reinterpret_cast<const float4*>(
            &x[((size_t)b * Tt + t0 + r) * Cc + c]);
        float w = srs[r];
        acc.x = fmaf(v.x, w, acc.x);
        acc.y = fmaf(v.y, w, acc.y);
        acc.z = fmaf(v.z, w, acc.z);
        acc.w = fmaf(v.w, w, acc.w);
    }
    *reinterpret_cast<float4*>(&partial[((size_t)b * NSP + sp) * Cc + c]) = acc;
}

__global__ __launch_bounds__(256)
void pooled_reduce_kernel(const float* partial, const float* S,
                          const float* __restrict__ lnw,
                          const float* __restrict__ lnb,
                          float* pooled) {
    int idx = blockIdx.x * 256 + threadIdx.x;
    int b = idx / Cc, c = idx % Cc;
    float a = 0.f;
    #pragma unroll
    for (int sp = 0; sp < NSP; sp++)
        a += partial[((size_t)b * NSP + sp) * Cc + c];
    pooled[idx] = lnw[c] * (a * (1.f / Tt) - S[b]) + lnb[c];
}

__global__ __launch_bounds__(256)
void gctx_kernel(const float* pooled,
                 const float* __restrict__ W,
                 const float* __restrict__ bias,
                 float* gctx) {
    int b  = blockIdx.x >> 4;
    int cb = blockIdx.x & 15;
    __shared__ float pb[Cc];
    __shared__ float red[256];
    for (int i = threadIdx.x; i < Cc; i += 256) pb[i] = pooled[b * Cc + i];
    __syncthreads();
    int o = threadIdx.x >> 2, ks = threadIdx.x & 3;
    int c = cb * 64 + o;
    float a = 0.f;
    int k0 = ks * 256;
    #pragma unroll 4
    for (int k = k0; k < k0 + 256; k++)
        a = fmaf(pb[k], W[(size_t)k * Cc + c], a);
    red[threadIdx.x] = a;
    __syncthreads();
    if (ks == 0) {
        float t = red[o*4] + red[o*4+1] + red[o*4+2] + red[o*4+3] + bias[c];
        gctx[b * Cc + c] = 1.f / (1.f + expf(-t));
    }
}

__device__ __forceinline__ float freq_mask_val(int f, int cut) {
    float mask = 1.f;
    if (cut < FB) {
        int tr = cut < 16 ? cut : 16;
        if (f >= cut) mask = 0.f;
        else if (tr > 0 && f >= cut - tr) {
            int i = f - (cut - tr);
            float tt = (tr > 1) ? (float)i / (float)(tr - 1) : 0.f;
            mask = 0.5f * (1.f + cospif(tt));
        }
    }
    return mask;
}

__global__ __launch_bounds__(256)
void freq_kernel(const float* __restrict__ kern,
                 const float* __restrict__ logits,
                 const int* __restrict__ cutp,
                 float* Wre, float* Wim) {
    __shared__ float ks[Kk];
    for (int i = threadIdx.x; i < Kk; i += 256) ks[i] = kern[i];
    __syncthreads();
    int f = blockIdx.x * 256 + threadIdx.x;
    if (f >= FB) return;
    float dc, ds;
    sincospif((float)f * (1.f / (NFFT / 2)), &ds, &dc);
    float re = 0.f, im = 0.f;
    for (int k0 = 0; k0 < Kk; k0 += 64) {
        int p = (f * k0) & (NFFT - 1);
        float c, sv;
        sincospif((float)p * (1.f / (NFFT / 2)), &sv, &c);
        #pragma unroll
        for (int k = k0; k < k0 + 64; k++) {
            float kv = ks[k];
            re = fmaf(kv,  c, re);
            im = fmaf(kv, -sv, im);
            float c2 = c * dc - sv * ds;
            sv = sv * dc + c * ds;
            c = c2;
        }
    }
    float g = 1.f / (1.f + expf(-logits[f]));
    float mask = freq_mask_val(f, *cutp);
    float coef = ((f == 0) || (f == NFFT / 2)) ? (1.f / NFFT) : (2.f / NFFT);
    float wgt = g * mask * coef;
    Wre[f] = re * wgt;
    Wim[f] = im * wgt;
}

__global__ __launch_bounds__(256)
void hfilt_kernel(const float* Wre, const float* Wim, float* h, float* flagp) {
    if (blockIdx.x == 0 && threadIdx.x == 0)
        *reinterpret_cast<int*>(flagp) = 0;
    __shared__ float sr[512], si[512];
    int s = blockIdx.x * 256 + threadIdx.x;
    float dc, dsn;
    sincospif((float)s * (1.f / (NFFT / 2)), &dsn, &dc);
    float acc = 0.f;
    for (int f0 = 0; f0 < FB; f0 += 512) {
        int n = min(512, FB - f0);
        __syncthreads();
        for (int i = threadIdx.x; i < n; i += 256) { sr[i] = Wre[f0 + i]; si[i] = Wim[f0 + i]; }
        __syncthreads();
        for (int ii = 0; ii < n; ii += 64) {
            int p = ((f0 + ii) * s) & (NFFT - 1);
            float c, sv;
            sincospif((float)p * (1.f / (NFFT / 2)), &sv, &c);
            int lim = min(ii + 64, n);
            #pragma unroll 4
            for (int i = ii; i < lim; i++) {
                acc = fmaf(sr[i],  c, acc);
                acc = fmaf(-si[i], sv, acc);
                float c2 = c * dc - sv * dsn;
                sv = sv * dc + c * dsn;
                c = c2;
            }
        }
    }
    h[s] = acc;
}

// ---------------------------------------------------------------------------
// Conv tile via bf16 MMA + ldmatrix (single-buffer, tile 128x128, K-chunk 64).
// As [128][64] stride 72; Bs [64][128] stride 136.
// ---------------------------------------------------------------------------
#define AS_HS 72
#define BS_HS 136

__device__ void conv_tile_mma(const float* __restrict__ x, float* out,
                              int b, int t0, int c0,
                              const float* sh_h,
                              const float* muArr, const float* rsArr,
                              const float* wsh, const float* bsh,
                              const float* __restrict__ gain,
                              const float* gctx_b,
                              __nv_bfloat16* As, __nv_bfloat16* Bs,
                              int tid) {
    const int lane = tid & 31, wid = tid >> 5;
    const int warp_m = wid & 3, warp_n = wid >> 2;
    const int bm = warp_m * 32, bn = warp_n * 64;
    const int r = lane >> 2, cq = lane & 3;
    const float* xb = x + (size_t)b * Tt * Cc;
    const int a_row = (lane & 15), a_koff = (lane >> 4) * 8;
    const int b_krow = (lane & 7) + ((lane >> 3) & 1) * 8;
    const int b_noff = (lane >> 4) * 8;

    float acc[2][8][4];
    #pragma unroll
    for (int mt = 0; mt < 2; mt++)
        #pragma unroll
        for (int nt = 0; nt < 8; nt++)
            #pragma unroll
            for (int j = 0; j < 4; j++) acc[mt][nt][j] = 0.f;

    for (int k0 = 0; k0 < Tt; k0 += 64) {
        #pragma unroll
        for (int l = 0; l < 4; l++) {
            int i = tid + l * 256;
            int m = i >> 3, k8 = (i & 7) * 8;
            int base = t0 + m - k0 - k8;
            uint4 v;
            v.x = pack_bf2(sh_h[(base    ) & (NFFT-1)], sh_h[(base - 1) & (NFFT-1)]);
            v.y = pack_bf2(sh_h[(base - 2) & (NFFT-1)], sh_h[(base - 3) & (NFFT-1)]);
            v.z = pack_bf2(sh_h[(base - 4) & (NFFT-1)], sh_h[(base - 5) & (NFFT-1)]);
            v.w = pack_bf2(sh_h[(base - 6) & (NFFT-1)], sh_h[(base - 7) & (NFFT-1)]);
            *reinterpret_cast<uint4*>(&As[m * AS_HS + k8]) = v;
        }
        #pragma unroll
        for (int l = 0; l < 8; l++) {
            int i = tid + l * 256;
            int u = i >> 5, cb = (i & 31) * 4;
            int ug = k0 + u;
            float rstd = rsArr[ug];
            float nmu  = -muArr[ug] * rstd;
            float4 xv = *reinterpret_cast<const float4*>(&xb[(size_t)ug * Cc + c0 + cb]);
            float v0 = fmaf(xv.x, rstd, nmu) * wsh[cb]     + bsh[cb];
            float v1 = fmaf(xv.y, rstd, nmu) * wsh[cb + 1] + bsh[cb + 1];
            float v2 = fmaf(xv.z, rstd, nmu) * wsh[cb + 2] + bsh[cb + 2];
            float v3 = fmaf(xv.w, rstd, nmu) * wsh[cb + 3] + bsh[cb + 3];
            uint2 pk;
            pk.x = pack_bf2(v0, v1);
            pk.y = pack_bf2(v2, v3);
            *reinterpret_cast<uint2*>(&Bs[u * BS_HS + cb]) = pk;
        }
        __syncthreads();
        #pragma unroll
        for (int s = 0; s < 4; s++) {
            int kk16 = s * 16;
            uint32_t a[2][4];
            #pragma unroll
            for (int mt = 0; mt < 2; mt++)
                ldsm4(a[mt][0], a[mt][1], a[mt][2], a[mt][3],
                      &As[(bm + mt * 16 + a_row) * AS_HS + kk16 + a_koff]);
            #pragma unroll
            for (int q = 0; q < 4; q++) {
                uint32_t t0r, t1r, t2r, t3r;
                ldsm4t(t0r, t1r, t2r, t3r,
                       &Bs[(kk16 + b_krow) * BS_HS + bn + q * 16 + b_noff]);
                mma16816(acc[0][2*q],   a[0], t0r, t1r);
                mma16816(acc[0][2*q+1], a[0], t2r, t3r);
                mma16816(acc[1][2*q],   a[1], t0r, t1r);
                mma16816(acc[1][2*q+1], a[1], t2r, t3r);
            }
        }
        __syncthreads();
    }

    #pragma unroll
    for (int mt = 0; mt < 2; mt++) {
        #pragma unroll
        for (int nt = 0; nt < 8; nt++) {
            int t = t0 + bm + mt * 16 + r;
            int c = c0 + bn + nt * 8 + cq * 2;
            float s0 = gain[c]     * gctx_b[c];
            float s1 = gain[c + 1] * gctx_b[c + 1];
            size_t ro = ((size_t)b * Tt + t) * Cc + c;
            float2 xr0 = *reinterpret_cast<const float2*>(&x[ro]);
            float2 o0;
            o0.x = xr0.x + acc[mt][nt][0] * s0;
            o0.y = xr0.y + acc[mt][nt][1] * s1;
            *reinterpret_cast<float2*>(&out[ro]) = o0;
            float2 xr1 = *reinterpret_cast<const float2*>(&x[ro + 8 * Cc]);
            float2 o1;
            o1.x = xr1.x + acc[mt][nt][2] * s0;
            o1.y = xr1.y + acc[mt][nt][3] * s1;
            *reinterpret_cast<float2*>(&out[ro + 8 * Cc]) = o1;
        }
    }
}

#define CONV_SMEM (32768 + 128*AS_HS*2 + 64*BS_HS*2)   // 68608

__global__ __launch_bounds__(256)
void conv_pass1_kernel(const float* __restrict__ x,
                       const float* __restrict__ lnw,
                       const float* __restrict__ lnb,
                       const float* __restrict__ gain,
                       float* out) {
    int b = blockIdx.z;
    if (b == 0 && blockIdx.y == 0) return;           // scratch tile -> fixup
    int t0 = blockIdx.y * 128;
    int c0 = blockIdx.x * 128;
    extern __shared__ char sm[];
    float* sh_h = reinterpret_cast<float*>(sm);
    __nv_bfloat16* As = reinterpret_cast<__nv_bfloat16*>(sm + 32768);
    __nv_bfloat16* Bs = reinterpret_cast<__nv_bfloat16*>(sm + 32768 + 128*AS_HS*2);
    __shared__ float wsh[128], bsh[128];
    int tid = threadIdx.x;
    const float* hG = out + OFF_H;
    for (int i = tid * 4; i < NFFT; i += 1024)
        *reinterpret_cast<float4*>(&sh_h[i]) = *reinterpret_cast<const float4*>(&hG[i]);
    if (tid < 128) { wsh[tid] = lnw[c0 + tid]; bsh[tid] = lnb[c0 + tid]; }
    __syncthreads();
    conv_tile_mma(x, out, b, t0, c0, sh_h,
                  out + OFF_MU + (size_t)b * Tt, out + OFF_RS + (size_t)b * Tt,
                  wsh, bsh, gain, out + OFF_GC + (size_t)b * Cc, As, Bs, tid);
}

#define FIXUP_SMEM (32768 + 16384 + 16384 + 128*AS_HS*2 + 64*BS_HS*2)  // 101376

__global__ __launch_bounds__(256)
void conv_fixup_kernel(const float* __restrict__ x,
                       const float* __restrict__ lnw,
                       const float* __restrict__ lnb,
                       const float* __restrict__ gain,
                       float* out) {
    extern __shared__ char sm[];
    float* sh_h = reinterpret_cast<float*>(sm);
    float* smu  = reinterpret_cast<float*>(sm + 32768);
    float* srs  = reinterpret_cast<float*>(sm + 49152);
    __nv_bfloat16* As = reinterpret_cast<__nv_bfloat16*>(sm + 65536);
    __nv_bfloat16* Bs = reinterpret_cast<__nv_bfloat16*>(sm + 65536 + 128*AS_HS*2);
    __shared__ float wsh[128], bsh[128], sgc[128];
    int tid = threadIdx.x;
    int c0 = blockIdx.x * 128;

    for (int i = tid; i < NFFT; i += 256) sh_h[i] = out[OFF_H + i];
    for (int i = tid; i < Tt; i += 256) {
        smu[i] = out[OFF_MU + i];
        srs[i] = out[OFF_RS + i];
    }
    if (tid < 128) {
        sgc[tid] = out[OFF_GC + c0 + tid];
        wsh[tid] = lnw[c0 + tid];
        bsh[tid] = lnb[c0 + tid];
    }
    __syncthreads();
    if (tid == 0) {       // all 8 co-resident blocks done copying scratch
        int* flag = reinterpret_cast<int*>(&out[OFF_FLAG]);
        atomicAdd(flag, 1);
        while (*reinterpret_cast<volatile int*>(flag) < 8) { }
    }
    __syncthreads();

    conv_tile_mma(x, out, 0, 0, c0, sh_h, smu, srs,
                  wsh, bsh, gain, sgc - c0, As, Bs, tid);
}

// ---------------------------------------------------------------------------
// Fused FFN via bf16 MMA + ldmatrix (resident sf, staged once before any
// in-place write; K-chunk 64, single-buffer, 256 threads, warps 2m x 4n).
// sf [64][1024] stride 1032; sht [64][256] stride 264; wst [64][256] str 264.
// ---------------------------------------------------------------------------
#define MT 64
#define SF_HS  1032
#define SHT_HS 264
#define WST_HS 264
#define FFN_SMEM (MT*SF_HS*2 + MT*SHT_HS*2 + 64*WST_HS*2)   // 199680

__global__ __launch_bounds__(256)
void ffn_kernel(float* out,
                const float* __restrict__ flnw, const float* __restrict__ flnb,
                const float* __restrict__ w1, const float* __restrict__ b1,
                const float* __restrict__ w2, const float* __restrict__ b2) {
    extern __shared__ char sm[];
    __nv_bfloat16* sf  = reinterpret_cast<__nv_bfloat16*>(sm);
    __nv_bfloat16* sht = reinterpret_cast<__nv_bfloat16*>(sm + MT*SF_HS*2);
    __nv_bfloat16* wst = reinterpret_cast<__nv_bfloat16*>(sm + MT*SF_HS*2 + MT*SHT_HS*2);
    __shared__ float smu[MT], srs[MT];

    int tid = threadIdx.x;
    size_t r0 = (size_t)blockIdx.x * MT;
    int lane = tid & 31, wid = tid >> 5;
    int warp_m = wid & 1, warp_n = wid >> 1;
    int bm = warp_m * 32, bn = warp_n * 64;
    int r = lane >> 2, cq = lane & 3;
    const int a_row = (lane & 15), a_koff = (lane >> 4) * 8;
    const int b_krow = (lane & 7) + ((lane >> 3) & 1) * 8;
    const int b_noff = (lane >> 4) * 8;

    // LN2 stats (warp per row)
    for (int rr = wid; rr < MT; rr += 8) {
        const float* row = out + (r0 + rr) * Cc;
        float s = 0.f, q = 0.f;
        for (int i = lane; i < Cc; i += 32) { float v = row[i]; s += v; q = fmaf(v, v, q); }
        for (int o = 16; o > 0; o >>= 1) {
            s += __shfl_xor_sync(0xFFFFFFFFu, s, o);
            q += __shfl_xor_sync(0xFFFFFFFFu, q, o);
        }
        if (lane == 0) {
            float m = s * (1.f / Cc);
            smu[rr] = m;
            srs[rr] = rsqrtf(q * (1.f / Cc) - m * m + EPSv);
        }
    }
    __syncthreads();

    // stage sf = LN(x2) bf16 (ONCE, before any write to out)
    for (int i = tid * 4; i < MT * Cc; i += 1024) {
        int row = i >> 10, col = i & 1023;
        float4 v = *reinterpret_cast<const float4*>(&out[(r0 + row) * Cc + col]);
        float rs = srs[row];
        float nmu = -smu[row] * rs;
        float4 wv = *reinterpret_cast<const float4*>(&flnw[col]);
        float4 bv = *reinterpret_cast<const float4*>(&flnb[col]);
        uint2 pk;
        pk.x = pack_bf2(fmaf(v.x, rs, nmu) * wv.x + bv.x, fmaf(v.y, rs, nmu) * wv.y + bv.y);
        pk.y = pack_bf2(fmaf(v.z, rs, nmu) * wv.z + bv.z, fmaf(v.w, rs, nmu) * wv.w + bv.w);
        *reinterpret_cast<uint2*>(&sf[row * SF_HS + col]) = pk;
    }
    __syncthreads();

    for (int hc = 0; hc < Hh; hc += 256) {
        // ---- GEMM1: sht[64,256] = gelu(sf @ w1[:,hc:hc+256] + b1) ----
        float acc[2][8][4];
        #pragma unroll
        for (int mt = 0; mt < 2; mt++)
            #pragma unroll
            for (int nt = 0; nt < 8; nt++)
                #pragma unroll
                for (int j = 0; j < 4; j++) acc[mt][nt][j] = 0.f;

        for (int k0 = 0; k0 < Cc; k0 += 64) {
            #pragma unroll
            for (int l = 0; l < 16; l++) {     // stage w1 [k=64][n=256]
                int i = tid + l * 256;
                int k = i >> 6, cb = (i & 63) * 4;
                float4 wv = *reinterpret_cast<const float4*>(
                    &w1[(size_t)(k0 + k) * Hh + hc + cb]);
                uint2 pk;
                pk.x = pack_bf2(wv.x, wv.y);
                pk.y = pack_bf2(wv.z, wv.w);
                *reinterpret_cast<uint2*>(&wst[k * WST_HS + cb]) = pk;
            }
            __syncthreads();
            #pragma unroll
            for (int s = 0; s < 4; s++) {
                int kk16 = s * 16;
                uint32_t a[2][4];
                #pragma unroll
                for (int mt = 0; mt < 2; mt++)
                    ldsm4(a[mt][0], a[mt][1], a[mt][2], a[mt][3],
                          &sf[(bm + mt * 16 + a_row) * SF_HS + k0 + kk16 + a_koff]);
                #pragma unroll
                for (int q = 0; q < 4; q++) {
                    uint32_t t0r, t1r, t2r, t3r;
                    ldsm4t(t0r, t1r, t2r, t3r,
                           &wst[(kk16 + b_krow) * WST_HS + bn + q * 16 + b_noff]);
                    mma16816(acc[0][2*q],   a[0], t0r, t1r);
                    mma16816(acc[0][2*q+1], a[0], t2r, t3r);
                    mma16816(acc[1][2*q],   a[1], t0r, t1r);
                    mma16816(acc[1][2*q+1], a[1], t2r, t3r);
                }
            }
            __syncthreads();
        }
        // epilogue1: bias + gelu -> sht
        #pragma unroll
        for (int mt = 0; mt < 2; mt++) {
            #pragma unroll
            for (int nt = 0; nt < 8; nt++) {
                int row = bm + mt * 16 + r;
                int col = bn + nt * 8 + cq * 2;
                float bb0 = b1[hc + col], bb1 = b1[hc + col + 1];
                float v0 = acc[mt][nt][0] + bb0;
                float v1 = acc[mt][nt][1] + bb1;
                float v2 = acc[mt][nt][2] + bb0;
                float v3 = acc[mt][nt][3] + bb1;
                v0 = 0.5f * v0 * (1.f + erff(v0 * 0.70710678118654752f));
                v1 = 0.5f * v1 * (1.f + erff(v1 * 0.70710678118654752f));
                v2 = 0.5f * v2 * (1.f + erff(v2 * 0.70710678118654752f));
                v3 = 0.5f * v3 * (1.f + erff(v3 * 0.70710678118654752f));
                *reinterpret_cast<uint32_t*>(&sht[row * SHT_HS + col])       = pack_bf2(v0, v1);
                *reinterpret_cast<uint32_t*>(&sht[(row + 8) * SHT_HS + col]) = pack_bf2(v2, v3);
            }
        }
        __syncthreads();

        // ---- GEMM2: out[64,:] += sht @ w2[hc:hc+256,:] (+ b2 on hc==0) ----
        for (int cc0 = 0; cc0 < Cc; cc0 += 256) {
            float acc2[2][8][4];
            #pragma unroll
            for (int mt = 0; mt < 2; mt++)
                #pragma unroll
                for (int nt = 0; nt < 8; nt++)
                    #pragma unroll
                    for (int j = 0; j < 4; j++) acc2[mt][nt][j] = 0.f;

            for (int k0 = 0; k0 < 256; k0 += 64) {
                #pragma unroll
                for (int l = 0; l < 16; l++) {     // stage w2 [k=64][n=256]
                    int i = tid + l * 256;
                    int k = i >> 6, cb = (i & 63) * 4;
                    float4 wv = *reinterpret_cast<const float4*>(
                        &w2[(size_t)(hc + k0 + k) * Cc + cc0 + cb]);
                    uint2 pk;
                    pk.x = pack_bf2(wv.x, wv.y);
                    pk.y = pack_bf2(wv.z, wv.w);
                    *reinterpret_cast<uint2*>(&wst[k * WST_HS + cb]) = pk;
                }
                __syncthreads();
                #pragma unroll
                for (int s = 0; s < 4; s++) {
                    int kk16 = s * 16;
                    uint32_t a[2][4];
                    #pragma unroll
                    for (int mt = 0; mt < 2; mt++)
                        ldsm4(a[mt][0], a[mt][1], a[mt][2], a[mt][3],
                              &sht[(bm + mt * 16 + a_row) * SHT_HS + k0 + kk16 + a_koff]);
                    #pragma unroll
                    for (int q = 0; q < 4; q++) {
                        uint32_t t0r, t1r, t2r, t3r;
                        ldsm4t(t0r, t1r, t2r, t3r,
                               &wst[(kk16 + b_krow) * WST_HS + bn + q * 16 + b_noff]);
                        mma16816(acc2[0][2*q],   a[0], t0r, t1r);
                        mma16816(acc2[0][2*q+1], a[0], t2r, t3r);
                        mma16816(acc2[1][2*q],   a[1], t0r, t1r);
                        mma16816(acc2[1][2*q+1], a[1], t2r, t3r);
                    }
                }
                __syncthreads();
            }
            // thread-private RMW into out (deterministic ownership)
            #pragma unroll
            for (int mt = 0; mt < 2; mt++) {
                #pragma unroll
                for (int nt = 0; nt < 8; nt++) {
                    int row = bm + mt * 16 + r;
                    int col = cc0 + bn + nt * 8 + cq * 2;
                    size_t ro = (r0 + row) * Cc + col;
                    float2 o0 = *reinterpret_cast<const float2*>(&out[ro]);
                    float2 o1 = *reinterpret_cast<const float2*>(&out[ro + 8 * Cc]);
                    if (hc == 0) {
                        float bb0 = b2[col], bb1 = b2[col + 1];
                        o0.x += bb0; o0.y += bb1;
                        o1.x += bb0; o1.y += bb1;
                    }
                    o0.x += acc2[mt][nt][0]; o0.y += acc2[mt][nt][1];
                    o1.x += acc2[mt][nt][2]; o1.y += acc2[mt][nt][3];
                    *reinterpret_cast<float2*>(&out[ro]) = o0;
                    *reinterpret_cast<float2*>(&out[ro + 8 * Cc]) = o1;
                }
            }
        }
        __syncthreads();
    }
}

// ---------------------------------------------------------------------------
// kernel_launch
// ---------------------------------------------------------------------------
extern "C" void kernel_launch(void* const* d_in, const int* in_sizes, int n_in,
                              void* d_out, int out_size) {
    const float* x    = (const float*)d_in[0];
    const float* kern = (const float*)d_in[1];
    const float* gain = (const float*)d_in[2];
    const float* gfl  = (const float*)d_in[3];
    const float* gcw  = (const float*)d_in[4];
    const float* gcb  = (const float*)d_in[5];
    const float* lnw  = (const float*)d_in[6];
    const float* lnb  = (const float*)d_in[7];
    const float* flnw = (const float*)d_in[8];
    const float* flnb = (const float*)d_in[9];
    const float* w1   = (const float*)d_in[10];
    const float* b1   = (const float*)d_in[11];
    const float* w2   = (const float*)d_in[12];
    const float* b2   = (const float*)d_in[13];
    const int*   cut  = (const int*)d_in[14];
    float* out = (float*)d_out;

    cudaFuncSetAttribute(conv_pass1_kernel,
                         cudaFuncAttributeMaxDynamicSharedMemorySize, CONV_SMEM);
    cudaFuncSetAttribute(conv_fixup_kernel,
                         cudaFuncAttributeMaxDynamicSharedMemorySize, FIXUP_SMEM);
    cudaFuncSetAttribute(ffn_kernel,
                         cudaFuncAttributeMaxDynamicSharedMemorySize, FFN_SMEM);

    ln_stats_kernel<<<NROWS, 256>>>(x, out + OFF_MU, out + OFF_RS);
    sred_kernel<<<Bb, 256>>>(out + OFF_MU, out + OFF_RS, out + OFF_S);
    pooled_part_kernel<<<dim3(NSP, Bb), 256>>>(x, out + OFF_RS, out + OFF_PP);
    pooled_reduce_kernel<<<(Bb * Cc) / 256, 256>>>(out + OFF_PP, out + OFF_S,
                                                   lnw, lnb, out + OFF_PL);
    gctx_kernel<<<Bb * (Cc / 64), 256>>>(out + OFF_PL, gcw, gcb, out + OFF_GC);
    freq_kernel<<<(FB + 255) / 256, 256>>>(kern, gfl, cut, out + OFF_WRE, out + OFF_WIM);
    hfilt_kernel<<<NFFT / 256, 256>>>(out + OFF_WRE, out + OFF_WIM,
                                      out + OFF_H, out + OFF_FLAG);
    conv_pass1_kernel<<<dim3(Cc / 128, Tt / 128, Bb), 256, CONV_SMEM>>>(
        x, lnw, lnb, gain, out);
    conv_fixup_kernel<<<8, 256, FIXUP_SMEM>>>(x, lnw, lnb, gain, out);
    ffn_kernel<<<NROWS / MT, 256, FFN_SMEM>>>(out, flnw, flnb, w1, b1, w2, b2);
}

// round 17
// speedup vs baseline: 1.1368x; 1.0128x over previous
#include <cuda_runtime.h>
#include <cuda_bf16.h>
#include <math.h>
#include <stdint.h>

// ---------------------------------------------------------------------------
// Problem constants (FixedSpectralBlock: B=4, T=4096, C=1024, K=1024)
// ---------------------------------------------------------------------------
#define Bb   4
#define Tt   4096
#define Cc   1024
#define Kk   1024
#define NFFT 8192
#define FB   4097          // NFFT/2 + 1
#define Hh   2048          // 2*C
#define EPSv 1e-5f
#define NROWS (Bb*Tt)
#define NSP  16            // pooled T-splits

// Scratch layout inside d_out rows 0..127 of batch 0 (conv pass-1 skips that
// tile; fixup reads scratch then overwrites it). Offsets in floats:
#define OFF_H     0        // hfilt          [8192]
#define OFF_WRE   8192     // W.re           [4160]
#define OFF_WIM   12352    // W.im           [4160]
#define OFF_MU    16512    // LN1 mean       [16384]
#define OFF_RS    32896    // LN1 rstd       [16384]
#define OFF_PL    49288    // pooled         [4096]
#define OFF_GC    53384    // gctx           [4096]
#define OFF_FLAG  58368    // 4 int flags: [0]=fixup [1]=freqh [2]=ctx1 [3]=ctx2
#define OFF_PP    58376    // pooled partials [Bb*NSP*Cc = 65536]
#define OFF_SPART 123912   // sred partials  [64]   (end 123976 < 131072)

// ---------------------------------------------------------------------------
// Helpers
// ---------------------------------------------------------------------------
__device__ __forceinline__ float2 block_reduce2(float a, float b) {
    __shared__ float sa[8], sb[8];
    for (int o = 16; o > 0; o >>= 1) {
        a += __shfl_xor_sync(0xFFFFFFFFu, a, o);
        b += __shfl_xor_sync(0xFFFFFFFFu, b, o);
    }
    int w = threadIdx.x >> 5, l = threadIdx.x & 31;
    if (l == 0) { sa[w] = a; sb[w] = b; }
    __syncthreads();
    if (w == 0) {
        a = (l < 8) ? sa[l] : 0.f;
        b = (l < 8) ? sb[l] : 0.f;
        for (int o = 4; o > 0; o >>= 1) {
            a += __shfl_xor_sync(0xFFFFFFFFu, a, o);
            b += __shfl_xor_sync(0xFFFFFFFFu, b, o);
        }
        if (l == 0) { sa[0] = a; sb[0] = b; }
    }
    __syncthreads();
    return make_float2(sa[0], sb[0]);
}

__device__ __forceinline__ uint32_t pack_bf2(float lo, float hi) {
    __nv_bfloat162 h = __floats2bfloat162_rn(lo, hi);
    return *reinterpret_cast<uint32_t*>(&h);
}

__device__ __forceinline__ uint32_t smem_cast(const void* p) {
    return (uint32_t)__cvta_generic_to_shared(p);
}

__device__ __forceinline__ void ldsm4(uint32_t& r0, uint32_t& r1,
                                      uint32_t& r2, uint32_t& r3,
                                      const void* p) {
    uint32_t a = smem_cast(p);
    asm volatile("ldmatrix.sync.aligned.m8n8.x4.shared.b16 {%0,%1,%2,%3},[%4];"
                 : "=r"(r0), "=r"(r1), "=r"(r2), "=r"(r3) : "r"(a));
}
__device__ __forceinline__ void ldsm4t(uint32_t& r0, uint32_t& r1,
                                       uint32_t& r2, uint32_t& r3,
                                       const void* p) {
    uint32_t a = smem_cast(p);
    asm volatile("ldmatrix.sync.aligned.m8n8.x4.trans.shared.b16 {%0,%1,%2,%3},[%4];"
                 : "=r"(r0), "=r"(r1), "=r"(r2), "=r"(r3) : "r"(a));
}

// m16n8k16 bf16 MMA, fp32 accumulate
__device__ __forceinline__ void mma16816(float* c, const uint32_t* a,
                                         uint32_t b0, uint32_t b1) {
    asm volatile(
        "mma.sync.aligned.m16n8k16.row.col.f32.bf16.bf16.f32 "
        "{%0,%1,%2,%3}, {%4,%5,%6,%7}, {%8,%9}, {%0,%1,%2,%3};\n"
        : "+f"(c[0]), "+f"(c[1]), "+f"(c[2]), "+f"(c[3])
        : "r"(a[0]), "r"(a[1]), "r"(a[2]), "r"(a[3]), "r"(b0), "r"(b1));
}

// Cross-block spin barrier (co-resident grids only).
__device__ __forceinline__ void grid_spin_barrier(int* flag, int nblocks) {
    __threadfence();
    __syncthreads();
    if (threadIdx.x == 0) {
        atomicAdd(flag, 1);
        while (*reinterpret_cast<volatile int*>(flag) < nblocks) { }
    }
    __syncthreads();
    __threadfence();
}

// ---------------------------------------------------------------------------
// Launch 1: per-row LN stats (+ flag reset). grid = NROWS, block = 256.
// ---------------------------------------------------------------------------
__global__ __launch_bounds__(256)
void ln_stats_kernel(const float* __restrict__ x, float* mu, float* rs,
                     float* flagp) {
    if (blockIdx.x == 0 && threadIdx.x < 4)
        reinterpret_cast<int*>(flagp)[threadIdx.x] = 0;
    size_t row = blockIdx.x;
    float4 v = reinterpret_cast<const float4*>(x + row * Cc)[threadIdx.x];
    float s  = v.x + v.y + v.z + v.w;
    float sq = v.x*v.x + v.y*v.y + v.z*v.z + v.w*v.w;
    float2 r = block_reduce2(s, sq);
    if (threadIdx.x == 0) {
        float mean = r.x * (1.f / Cc);
        float var  = r.y * (1.f / Cc) - mean * mean;
        mu[row] = mean;
        rs[row] = rsqrtf(var + EPSv);
    }
}

// ---------------------------------------------------------------------------
// Launch 2: fused filter spectrum + time-domain filter. 32 blocks x 256.
// Phase 1: W[f] (8192 threads cover FB=4097). Spin barrier. Phase 2: h[s].
// ---------------------------------------------------------------------------
__device__ __forceinline__ float freq_mask_val(int f, int cut) {
    float mask = 1.f;
    if (cut < FB) {
        int tr = cut < 16 ? cut : 16;
        if (f >= cut) mask = 0.f;
        else if (tr > 0 && f >= cut - tr) {
            int i = f - (cut - tr);
            float tt = (tr > 1) ? (float)i / (float)(tr - 1) : 0.f;
            mask = 0.5f * (1.f + cospif(tt));
        }
    }
    return mask;
}

__global__ __launch_bounds__(256)
void freqh_kernel(const float* __restrict__ kern,
                  const float* __restrict__ logits,
                  const int* __restrict__ cutp,
                  float* out) {
    float* Wre = out + OFF_WRE;
    float* Wim = out + OFF_WIM;
    float* h   = out + OFF_H;
    int* flag  = reinterpret_cast<int*>(&out[OFF_FLAG]) + 1;
    __shared__ float smbuf[Kk];            // phase1: kernel taps; phase2: sr|si
    int tid = threadIdx.x;

    // ---- phase 1: W spectrum ----
    for (int i = tid; i < Kk; i += 256) smbuf[i] = kern[i];
    __syncthreads();
    int f = blockIdx.x * 256 + tid;
    if (f < FB) {
        float dc, ds;
        sincospif((float)f * (1.f / (NFFT / 2)), &ds, &dc);
        float re = 0.f, im = 0.f;
        for (int k0 = 0; k0 < Kk; k0 += 64) {
            int p = (f * k0) & (NFFT - 1);
            float c, sv;
            sincospif((float)p * (1.f / (NFFT / 2)), &sv, &c);
            #pragma unroll
            for (int k = k0; k < k0 + 64; k++) {
                float kv = smbuf[k];
                re = fmaf(kv,  c, re);
                im = fmaf(kv, -sv, im);
                float c2 = c * dc - sv * ds;
                sv = sv * dc + c * ds;
                c = c2;
            }
        }
        float g = 1.f / (1.f + expf(-logits[f]));
        float mask = freq_mask_val(f, *cutp);
        float coef = ((f == 0) || (f == NFFT / 2)) ? (1.f / NFFT) : (2.f / NFFT);
        float wgt = g * mask * coef;
        Wre[f] = re * wgt;
        Wim[f] = im * wgt;
    }
    grid_spin_barrier(flag, 32);

    // ---- phase 2: h synthesis ----
    float* sr = smbuf;
    float* si = smbuf + 512;
    int s = blockIdx.x * 256 + tid;
    float dc, dsn;
    sincospif((float)s * (1.f / (NFFT / 2)), &dsn, &dc);
    float acc = 0.f;
    for (int f0 = 0; f0 < FB; f0 += 512) {
        int n = min(512, FB - f0);
        __syncthreads();
        for (int i = tid; i < n; i += 256) { sr[i] = Wre[f0 + i]; si[i] = Wim[f0 + i]; }
        __syncthreads();
        for (int ii = 0; ii < n; ii += 64) {
            int p = ((f0 + ii) * s) & (NFFT - 1);
            float c, sv;
            sincospif((float)p * (1.f / (NFFT / 2)), &sv, &c);
            int lim = min(ii + 64, n);
            #pragma unroll 4
            for (int i = ii; i < lim; i++) {
                acc = fmaf(sr[i],  c, acc);
                acc = fmaf(-si[i], sv, acc);
                float c2 = c * dc - sv * dsn;
                sv = sv * dc + c * dsn;
                c = c2;
            }
        }
    }
    h[s] = acc;
}

// ---------------------------------------------------------------------------
// Launch 3: fused context gate. 64 blocks x 256.
// Phase 1: pooled partials + sred partials. Barrier. Phase 2: pooled.
// Barrier. Phase 3: gctx GEMV.
// ---------------------------------------------------------------------------
__global__ __launch_bounds__(256)
void ctx_kernel(const float* __restrict__ x,
                const float* __restrict__ gcw,
                const float* __restrict__ gcb,
                const float* __restrict__ lnw,
                const float* __restrict__ lnb,
                float* out) {
    const float* mu = out + OFF_MU;
    const float* rs = out + OFF_RS;
    float* PP    = out + OFF_PP;
    float* SPART = out + OFF_SPART;
    float* pooled = out + OFF_PL;
    float* gctx   = out + OFF_GC;
    int* flag1 = reinterpret_cast<int*>(&out[OFF_FLAG]) + 2;
    int* flag2 = reinterpret_cast<int*>(&out[OFF_FLAG]) + 3;
    __shared__ float pb[Cc];
    __shared__ float red[256];
    int tid = threadIdx.x;

    // ---- phase 1: partials over this block's T-slice ----
    {
        int b = blockIdx.x >> 4, sp = blockIdx.x & 15;
        int t0 = sp * (Tt / NSP);
        red[tid] = rs[b * Tt + t0 + tid];                 // rs slice (256 rows)
        float a = mu[b * Tt + t0 + tid] * red[tid];       // mu*rs for sred
        float2 rr = block_reduce2(a, 0.f);                // includes syncthreads
        if (tid == 0) SPART[blockIdx.x] = rr.x;
        int c = tid * 4;
        float4 acc = make_float4(0.f, 0.f, 0.f, 0.f);
        for (int r = 0; r < Tt / NSP; r++) {
            float4 v = *reinterpret_cast<const float4*>(
                &x[((size_t)b * Tt + t0 + r) * Cc + c]);
            float w = red[r];
            acc.x = fmaf(v.x, w, acc.x);
            acc.y = fmaf(v.y, w, acc.y);
            acc.z = fmaf(v.z, w, acc.z);
            acc.w = fmaf(v.w, w, acc.w);
        }
        *reinterpret_cast<float4*>(&PP[((size_t)b * NSP + sp) * Cc + c]) = acc;
    }
    grid_spin_barrier(flag1, 64);

    // ---- phase 2: pooled (16 working blocks) ----
    if (blockIdx.x < 16) {
        int b = blockIdx.x >> 2, c0 = (blockIdx.x & 3) * 256;
        int c = c0 + tid;
        float Sb = 0.f;
        #pragma unroll
        for (int sp = 0; sp < NSP; sp++) Sb += SPART[b * NSP + sp];
        float a = 0.f;
        #pragma unroll
        for (int sp = 0; sp < NSP; sp++)
            a += PP[((size_t)b * NSP + sp) * Cc + c];
        pooled[b * Cc + c] = lnw[c] * ((a - Sb) * (1.f / Tt)) + lnb[c];
    }
    grid_spin_barrier(flag2, 64);

    // ---- phase 3: gctx GEMV (split-K x4) ----
    {
        int b  = blockIdx.x >> 4;
        int cb = blockIdx.x & 15;
        for (int i = tid; i < Cc; i += 256) pb[i] = pooled[b * Cc + i];
        __syncthreads();
        int o = tid >> 2, ks = tid & 3;
        int c = cb * 64 + o;
        float a = 0.f;
        int k0 = ks * 256;
        #pragma unroll 4
        for (int k = k0; k < k0 + 256; k++)
            a = fmaf(pb[k], gcw[(size_t)k * Cc + c], a);
        red[tid] = a;
        __syncthreads();
        if (ks == 0) {
            float t = red[o*4] + red[o*4+1] + red[o*4+2] + red[o*4+3] + gcb[c];
            gctx[b * Cc + c] = 1.f / (1.f + expf(-t));
        }
    }
}

// ---------------------------------------------------------------------------
// Conv tile via bf16 MMA + ldmatrix (single-buffer, tile 128x128, K-chunk 64).
// As [128][64] stride 72; Bs [64][128] stride 136.
// ---------------------------------------------------------------------------
#define AS_HS 72
#define BS_HS 136

__device__ void conv_tile_mma(const float* __restrict__ x, float* out,
                              int b, int t0, int c0,
                              const float* sh_h,
                              const float* muArr, const float* rsArr,
                              const float* wsh, const float* bsh,
                              const float* __restrict__ gain,
                              const float* gctx_b,
                              __nv_bfloat16* As, __nv_bfloat16* Bs,
                              int tid) {
    const int lane = tid & 31, wid = tid >> 5;
    const int warp_m = wid & 3, warp_n = wid >> 2;
    const int bm = warp_m * 32, bn = warp_n * 64;
    const int r = lane >> 2, cq = lane & 3;
    const float* xb = x + (size_t)b * Tt * Cc;
    const int a_row = (lane & 15), a_koff = (lane >> 4) * 8;
    const int b_krow = (lane & 7) + ((lane >> 3) & 1) * 8;
    const int b_noff = (lane >> 4) * 8;

    float acc[2][8][4];
    #pragma unroll
    for (int mt = 0; mt < 2; mt++)
        #pragma unroll
        for (int nt = 0; nt < 8; nt++)
            #pragma unroll
            for (int j = 0; j < 4; j++) acc[mt][nt][j] = 0.f;

    for (int k0 = 0; k0 < Tt; k0 += 64) {
        #pragma unroll
        for (int l = 0; l < 4; l++) {
            int i = tid + l * 256;
            int m = i >> 3, k8 = (i & 7) * 8;
            int base = t0 + m - k0 - k8;
            uint4 v;
            v.x = pack_bf2(sh_h[(base    ) & (NFFT-1)], sh_h[(base - 1) & (NFFT-1)]);
            v.y = pack_bf2(sh_h[(base - 2) & (NFFT-1)], sh_h[(base - 3) & (NFFT-1)]);
            v.z = pack_bf2(sh_h[(base - 4) & (NFFT-1)], sh_h[(base - 5) & (NFFT-1)]);
            v.w = pack_bf2(sh_h[(base - 6) & (NFFT-1)], sh_h[(base - 7) & (NFFT-1)]);
            *reinterpret_cast<uint4*>(&As[m * AS_HS + k8]) = v;
        }
        #pragma unroll
        for (int l = 0; l < 8; l++) {
            int i = tid + l * 256;
            int u = i >> 5, cb = (i & 31) * 4;
            int ug = k0 + u;
            float rstd = rsArr[ug];
            float nmu  = -muArr[ug] * rstd;
            float4 xv = *reinterpret_cast<const float4*>(&xb[(size_t)ug * Cc + c0 + cb]);
            float v0 = fmaf(xv.x, rstd, nmu) * wsh[cb]     + bsh[cb];
            float v1 = fmaf(xv.y, rstd, nmu) * wsh[cb + 1] + bsh[cb + 1];
            float v2 = fmaf(xv.z, rstd, nmu) * wsh[cb + 2] + bsh[cb + 2];
            float v3 = fmaf(xv.w, rstd, nmu) * wsh[cb + 3] + bsh[cb + 3];
            uint2 pk;
            pk.x = pack_bf2(v0, v1);
            pk.y = pack_bf2(v2, v3);
            *reinterpret_cast<uint2*>(&Bs[u * BS_HS + cb]) = pk;
        }
        __syncthreads();
        #pragma unroll
        for (int s = 0; s < 4; s++) {
            int kk16 = s * 16;
            uint32_t a[2][4];
            #pragma unroll
            for (int mt = 0; mt < 2; mt++)
                ldsm4(a[mt][0], a[mt][1], a[mt][2], a[mt][3],
                      &As[(bm + mt * 16 + a_row) * AS_HS + kk16 + a_koff]);
            #pragma unroll
            for (int q = 0; q < 4; q++) {
                uint32_t t0r, t1r, t2r, t3r;
                ldsm4t(t0r, t1r, t2r, t3r,
                       &Bs[(kk16 + b_krow) * BS_HS + bn + q * 16 + b_noff]);
                mma16816(acc[0][2*q],   a[0], t0r, t1r);
                mma16816(acc[0][2*q+1], a[0], t2r, t3r);
                mma16816(acc[1][2*q],   a[1], t0r, t1r);
                mma16816(acc[1][2*q+1], a[1], t2r, t3r);
            }
        }
        __syncthreads();
    }

    #pragma unroll
    for (int mt = 0; mt < 2; mt++) {
        #pragma unroll
        for (int nt = 0; nt < 8; nt++) {
            int t = t0 + bm + mt * 16 + r;
            int c = c0 + bn + nt * 8 + cq * 2;
            float s0 = gain[c]     * gctx_b[c];
            float s1 = gain[c + 1] * gctx_b[c + 1];
            size_t ro = ((size_t)b * Tt + t) * Cc + c;
            float2 xr0 = *reinterpret_cast<const float2*>(&x[ro]);
            float2 o0;
            o0.x = xr0.x + acc[mt][nt][0] * s0;
            o0.y = xr0.y + acc[mt][nt][1] * s1;
            *reinterpret_cast<float2*>(&out[ro]) = o0;
            float2 xr1 = *reinterpret_cast<const float2*>(&x[ro + 8 * Cc]);
            float2 o1;
            o1.x = xr1.x + acc[mt][nt][2] * s0;
            o1.y = xr1.y + acc[mt][nt][3] * s1;
            *reinterpret_cast<float2*>(&out[ro + 8 * Cc]) = o1;
        }
    }
}

#define CONV_SMEM (32768 + 128*AS_HS*2 + 64*BS_HS*2)   // 68608

__global__ __launch_bounds__(256)
void conv_pass1_kernel(const float* __restrict__ x,
                       const float* __restrict__ lnw,
                       const float* __restrict__ lnb,
                       const float* __restrict__ gain,
                       float* out) {
    int b = blockIdx.z;
    if (b == 0 && blockIdx.y == 0) return;           // scratch tile -> fixup
    int t0 = blockIdx.y * 128;
    int c0 = blockIdx.x * 128;
    extern __shared__ char sm[];
    float* sh_h = reinterpret_cast<float*>(sm);
    __nv_bfloat16* As = reinterpret_cast<__nv_bfloat16*>(sm + 32768);
    __nv_bfloat16* Bs = reinterpret_cast<__nv_bfloat16*>(sm + 32768 + 128*AS_HS*2);
    __shared__ float wsh[128], bsh[128];
    int tid = threadIdx.x;
    const float* hG = out + OFF_H;
    for (int i = tid * 4; i < NFFT; i += 1024)
        *reinterpret_cast<float4*>(&sh_h[i]) = *reinterpret_cast<const float4*>(&hG[i]);
    if (tid < 128) { wsh[tid] = lnw[c0 + tid]; bsh[tid] = lnb[c0 + tid]; }
    __syncthreads();
    conv_tile_mma(x, out, b, t0, c0, sh_h,
                  out + OFF_MU + (size_t)b * Tt, out + OFF_RS + (size_t)b * Tt,
                  wsh, bsh, gain, out + OFF_GC + (size_t)b * Cc, As, Bs, tid);
}

#define FIXUP_SMEM (32768 + 16384 + 16384 + 128*AS_HS*2 + 64*BS_HS*2)  // 101376

__global__ __launch_bounds__(256)
void conv_fixup_kernel(const float* __restrict__ x,
                       const float* __restrict__ lnw,
                       const float* __restrict__ lnb,
                       const float* __restrict__ gain,
                       float* out) {
    extern __shared__ char sm[];
    float* sh_h = reinterpret_cast<float*>(sm);
    float* smu  = reinterpret_cast<float*>(sm + 32768);
    float* srs  = reinterpret_cast<float*>(sm + 49152);
    __nv_bfloat16* As = reinterpret_cast<__nv_bfloat16*>(sm + 65536);
    __nv_bfloat16* Bs = reinterpret_cast<__nv_bfloat16*>(sm + 65536 + 128*AS_HS*2);
    __shared__ float wsh[128], bsh[128], sgc[128];
    int tid = threadIdx.x;
    int c0 = blockIdx.x * 128;

    for (int i = tid; i < NFFT; i += 256) sh_h[i] = out[OFF_H + i];
    for (int i = tid; i < Tt; i += 256) {
        smu[i] = out[OFF_MU + i];
        srs[i] = out[OFF_RS + i];
    }
    if (tid < 128) {
        sgc[tid] = out[OFF_GC + c0 + tid];
        wsh[tid] = lnw[c0 + tid];
        bsh[tid] = lnb[c0 + tid];
    }
    grid_spin_barrier(reinterpret_cast<int*>(&out[OFF_FLAG]), 8);

    conv_tile_mma(x, out, 0, 0, c0, sh_h, smu, srs,
                  wsh, bsh, gain, sgc - c0, As, Bs, tid);
}

// ---------------------------------------------------------------------------
// Fused FFN via bf16 MMA + ldmatrix (resident sf, staged once before any
// in-place write; K-chunk 64, single-buffer, 256 threads, warps 2m x 4n).
// ---------------------------------------------------------------------------
#define MT 64
#define SF_HS  1032
#define SHT_HS 264
#define WST_HS 264
#define FFN_SMEM (MT*SF_HS*2 + MT*SHT_HS*2 + 64*WST_HS*2)   // 199680

__global__ __launch_bounds__(256)
void ffn_kernel(float* out,
                const float* __restrict__ flnw, const float* __restrict__ flnb,
                const float* __restrict__ w1, const float* __restrict__ b1,
                const float* __restrict__ w2, const float* __restrict__ b2) {
    extern __shared__ char sm[];
    __nv_bfloat16* sf  = reinterpret_cast<__nv_bfloat16*>(sm);
    __nv_bfloat16* sht = reinterpret_cast<__nv_bfloat16*>(sm + MT*SF_HS*2);
    __nv_bfloat16* wst = reinterpret_cast<__nv_bfloat16*>(sm + MT*SF_HS*2 + MT*SHT_HS*2);
    __shared__ float smu[MT], srs[MT];

    int tid = threadIdx.x;
    size_t r0 = (size_t)blockIdx.x * MT;
    int lane = tid & 31, wid = tid >> 5;
    int warp_m = wid & 1, warp_n = wid >> 1;
    int bm = warp_m * 32, bn = warp_n * 64;
    int r = lane >> 2, cq = lane & 3;
    const int a_row = (lane & 15), a_koff = (lane >> 4) * 8;
    const int b_krow = (lane & 7) + ((lane >> 3) & 1) * 8;
    const int b_noff = (lane >> 4) * 8;

    for (int rr = wid; rr < MT; rr += 8) {
        const float* row = out + (r0 + rr) * Cc;
        float s = 0.f, q = 0.f;
        for (int i = lane; i < Cc; i += 32) { float v = row[i]; s += v; q = fmaf(v, v, q); }
        for (int o = 16; o > 0; o >>= 1) {
            s += __shfl_xor_sync(0xFFFFFFFFu, s, o);
            q += __shfl_xor_sync(0xFFFFFFFFu, q, o);
        }
        if (lane == 0) {
            float m = s * (1.f / Cc);
            smu[rr] = m;
            srs[rr] = rsqrtf(q * (1.f / Cc) - m * m + EPSv);
        }
    }
    __syncthreads();

    for (int i = tid * 4; i < MT * Cc; i += 1024) {
        int row = i >> 10, col = i & 1023;
        float4 v = *reinterpret_cast<const float4*>(&out[(r0 + row) * Cc + col]);
        float rs = srs[row];
        float nmu = -smu[row] * rs;
        float4 wv = *reinterpret_cast<const float4*>(&flnw[col]);
        float4 bv = *reinterpret_cast<const float4*>(&flnb[col]);
        uint2 pk;
        pk.x = pack_bf2(fmaf(v.x, rs, nmu) * wv.x + bv.x, fmaf(v.y, rs, nmu) * wv.y + bv.y);
        pk.y = pack_bf2(fmaf(v.z, rs, nmu) * wv.z + bv.z, fmaf(v.w, rs, nmu) * wv.w + bv.w);
        *reinterpret_cast<uint2*>(&sf[row * SF_HS + col]) = pk;
    }
    __syncthreads();

    for (int hc = 0; hc < Hh; hc += 256) {
        float acc[2][8][4];
        #pragma unroll
        for (int mt = 0; mt < 2; mt++)
            #pragma unroll
            for (int nt = 0; nt < 8; nt++)
                #pragma unroll
                for (int j = 0; j < 4; j++) acc[mt][nt][j] = 0.f;

        for (int k0 = 0; k0 < Cc; k0 += 64) {
            #pragma unroll
            for (int l = 0; l < 16; l++) {
                int i = tid + l * 256;
                int k = i >> 6, cb = (i & 63) * 4;
                float4 wv = *reinterpret_cast<const float4*>(
                    &w1[(size_t)(k0 + k) * Hh + hc + cb]);
                uint2 pk;
                pk.x = pack_bf2(wv.x, wv.y);
                pk.y = pack_bf2(wv.z, wv.w);
                *reinterpret_cast<uint2*>(&wst[k * WST_HS + cb]) = pk;
            }
            __syncthreads();
            #pragma unroll
            for (int s = 0; s < 4; s++) {
                int kk16 = s * 16;
                uint32_t a[2][4];
                #pragma unroll
                for (int mt = 0; mt < 2; mt++)
                    ldsm4(a[mt][0], a[mt][1], a[mt][2], a[mt][3],
                          &sf[(bm + mt * 16 + a_row) * SF_HS + k0 + kk16 + a_koff]);
                #pragma unroll
                for (int q = 0; q < 4; q++) {
                    uint32_t t0r, t1r, t2r, t3r;
                    ldsm4t(t0r, t1r, t2r, t3r,
                           &wst[(kk16 + b_krow) * WST_HS + bn + q * 16 + b_noff]);
                    mma16816(acc[0][2*q],   a[0], t0r, t1r);
                    mma16816(acc[0][2*q+1], a[0], t2r, t3r);
                    mma16816(acc[1][2*q],   a[1], t0r, t1r);
                    mma16816(acc[1][2*q+1], a[1], t2r, t3r);
                }
            }
            __syncthreads();
        }
        #pragma unroll
        for (int mt = 0; mt < 2; mt++) {
            #pragma unroll
            for (int nt = 0; nt < 8; nt++) {
                int row = bm + mt * 16 + r;
                int col = bn + nt * 8 + cq * 2;
                float bb0 = b1[hc + col], bb1 = b1[hc + col + 1];
                float v0 = acc[mt][nt][0] + bb0;
                float v1 = acc[mt][nt][1] + bb1;
                float v2 = acc[mt][nt][2] + bb0;
                float v3 = acc[mt][nt][3] + bb1;
                v0 = 0.5f * v0 * (1.f + erff(v0 * 0.70710678118654752f));
                v1 = 0.5f * v1 * (1.f + erff(v1 * 0.70710678118654752f));
                v2 = 0.5f * v2 * (1.f + erff(v2 * 0.70710678118654752f));
                v3 = 0.5f * v3 * (1.f + erff(v3 * 0.70710678118654752f));
                *reinterpret_cast<uint32_t*>(&sht[row * SHT_HS + col])       = pack_bf2(v0, v1);
                *reinterpret_cast<uint32_t*>(&sht[(row + 8) * SHT_HS + col]) = pack_bf2(v2, v3);
            }
        }
        __syncthreads();

        for (int cc0 = 0; cc0 < Cc; cc0 += 256) {
            float acc2[2][8][4];
            #pragma unroll
            for (int mt = 0; mt < 2; mt++)
                #pragma unroll
                for (int nt = 0; nt < 8; nt++)
                    #pragma unroll
                    for (int j = 0; j < 4; j++) acc2[mt][nt][j] = 0.f;

            for (int k0 = 0; k0 < 256; k0 += 64) {
                #pragma unroll
                for (int l = 0; l < 16; l++) {
                    int i = tid + l * 256;
                    int k = i >> 6, cb = (i & 63) * 4;
                    float4 wv = *reinterpret_cast<const float4*>(
                        &w2[(size_t)(hc + k0 + k) * Cc + cc0 + cb]);
                    uint2 pk;
                    pk.x = pack_bf2(wv.x, wv.y);
                    pk.y = pack_bf2(wv.z, wv.w);
                    *reinterpret_cast<uint2*>(&wst[k * WST_HS + cb]) = pk;
                }
                __syncthreads();
                #pragma unroll
                for (int s = 0; s < 4; s++) {
                    int kk16 = s * 16;
                    uint32_t a[2][4];
                    #pragma unroll
                    for (int mt = 0; mt < 2; mt++)
                        ldsm4(a[mt][0], a[mt][1], a[mt][2], a[mt][3],
                              &sht[(bm + mt * 16 + a_row) * SHT_HS + k0 + kk16 + a_koff]);
                    #pragma unroll
                    for (int q = 0; q < 4; q++) {
                        uint32_t t0r, t1r, t2r, t3r;
                        ldsm4t(t0r, t1r, t2r, t3r,
                               &wst[(kk16 + b_krow) * WST_HS + bn + q * 16 + b_noff]);
                        mma16816(acc2[0][2*q],   a[0], t0r, t1r);
                        mma16816(acc2[0][2*q+1], a[0], t2r, t3r);
                        mma16816(acc2[1][2*q],   a[1], t0r, t1r);
                        mma16816(acc2[1][2*q+1], a[1], t2r, t3r);
                    }
                }
                __syncthreads();
            }
            #pragma unroll
            for (int mt = 0; mt < 2; mt++) {
                #pragma unroll
                for (int nt = 0; nt < 8; nt++) {
                    int row = bm + mt * 16 + r;
                    int col = cc0 + bn + nt * 8 + cq * 2;
                    size_t ro = (r0 + row) * Cc + col;
                    float2 o0 = *reinterpret_cast<const float2*>(&out[ro]);
                    float2 o1 = *reinterpret_cast<const float2*>(&out[ro + 8 * Cc]);
                    if (hc == 0) {
                        float bb0 = b2[col], bb1 = b2[col + 1];
                        o0.x += bb0; o0.y += bb1;
                        o1.x += bb0; o1.y += bb1;
                    }
                    o0.x += acc2[mt][nt][0]; o0.y += acc2[mt][nt][1];
                    o1.x += acc2[mt][nt][2]; o1.y += acc2[mt][nt][3];
                    *reinterpret_cast<float2*>(&out[ro]) = o0;
                    *reinterpret_cast<float2*>(&out[ro + 8 * Cc]) = o1;
                }
            }
        }
        __syncthreads();
    }
}

// ---------------------------------------------------------------------------
// kernel_launch — 6 launches; #4 = conv_pass1 (ncu capture slot).
// ---------------------------------------------------------------------------
extern "C" void kernel_launch(void* const* d_in, const int* in_sizes, int n_in,
                              void* d_out, int out_size) {
    const float* x    = (const float*)d_in[0];
    const float* kern = (const float*)d_in[1];
    const float* gain = (const float*)d_in[2];
    const float* gfl  = (const float*)d_in[3];
    const float* gcw  = (const float*)d_in[4];
    const float* gcb  = (const float*)d_in[5];
    const float* lnw  = (const float*)d_in[6];
    const float* lnb  = (const float*)d_in[7];
    const float* flnw = (const float*)d_in[8];
    const float* flnb = (const float*)d_in[9];
    const float* w1   = (const float*)d_in[10];
    const float* b1   = (const float*)d_in[11];
    const float* w2   = (const float*)d_in[12];
    const float* b2   = (const float*)d_in[13];
    const int*   cut  = (const int*)d_in[14];
    float* out = (float*)d_out;

    cudaFuncSetAttribute(conv_pass1_kernel,
                         cudaFuncAttributeMaxDynamicSharedMemorySize, CONV_SMEM);
    cudaFuncSetAttribute(conv_fixup_kernel,
                         cudaFuncAttributeMaxDynamicSharedMemorySize, FIXUP_SMEM);
    cudaFuncSetAttribute(ffn_kernel,
                         cudaFuncAttributeMaxDynamicSharedMemorySize, FFN_SMEM);

    // 1. LN stats (+ flag reset)
    ln_stats_kernel<<<NROWS, 256>>>(x, out + OFF_MU, out + OFF_RS, out + OFF_FLAG);
    // 2. fused filter spectrum + h
    freqh_kernel<<<32, 256>>>(kern, gfl, cut, out);
    // 3. fused pooled + gctx
    ctx_kernel<<<64, 256>>>(x, gcw, gcb, lnw, lnb, out);
    // 4. conv GEMM pass 1  <-- ncu capture slot
    conv_pass1_kernel<<<dim3(Cc / 128, Tt / 128, Bb), 256, CONV_SMEM>>>(
        x, lnw, lnb, gain, out);
    // 5. conv fixup (rewrites scratch tile)
    conv_fixup_kernel<<<8, 256, FIXUP_SMEM>>>(x, lnw, lnb, gain, out);
    // 6. fused FFN
    ffn_kernel<<<NROWS / MT, 256, FFN_SMEM>>>(out, flnw, flnb, w1, b1, w2, b2);
}